// round 8
// baseline (speedup 1.0000x reference)
#include <cuda_runtime.h>
#include <cuda_bf16.h>
#include <cstdint>

#define NTOK 4096
#define EMB  768
#define NH   12
#define HD   64
#define PADB 72
#define L2E  1.4426950408889634f

// ---------------------------------------------------------------------------
// Scratch (allocation-free device globals)
// ---------------------------------------------------------------------------
__device__ __align__(16) __nv_bfloat16 g_xhi[NTOK * EMB];
__device__ __align__(16) __nv_bfloat16 g_xlo[NTOK * EMB];
__device__ __align__(16) __nv_bfloat16 g_whi[4 * EMB * EMB];
__device__ __align__(16) __nv_bfloat16 g_wlo[4 * EMB * EMB];
__device__ __align__(16) __nv_bfloat16 g_qhi[NH * NTOK * HD];
__device__ __align__(16) __nv_bfloat16 g_qlo[NH * NTOK * HD];
__device__ __align__(16) __nv_bfloat16 g_khi[NH * NTOK * HD];
__device__ __align__(16) __nv_bfloat16 g_klo[NH * NTOK * HD];
__device__ __align__(16) __nv_bfloat16 g_vhi[NH * NTOK * HD];
__device__ __align__(16) __nv_bfloat16 g_vlo[NH * NTOK * HD];
__device__ __align__(16) __nv_bfloat16 g_vthi[NH * HD * NTOK];
__device__ __align__(16) __nv_bfloat16 g_vtlo[NH * HD * NTOK];

// ---------------------------------------------------------------------------
// Helpers
// ---------------------------------------------------------------------------
__device__ __forceinline__ uint32_t pack_bf16x2(float lo, float hi) {
    uint32_t r;
    asm("cvt.rn.bf16x2.f32 %0, %1, %2;" : "=r"(r) : "f"(hi), "f"(lo));
    return r;
}

// fast exp2 on the FMA pipe, input <= 0
__device__ __forceinline__ float exp2p(float t) {
    t = fmaxf(t, -120.f);
    float z  = t + 12582912.f;            // 1.5 * 2^23
    float fi = z - 12582912.f;
    float f  = t - fi;
    float p = fmaf(0.00133335581f, f, 0.00961812911f);
    p = fmaf(p, f, 0.0555041087f);
    p = fmaf(p, f, 0.240226507f);
    p = fmaf(p, f, 0.69314718056f);
    p = fmaf(p, f, 1.0f);
    return p * __int_as_float((__float_as_int(z) + 127) << 23);
}

#define MMA_BF16(d, a, b0, b1)                                             \
    asm volatile(                                                          \
        "mma.sync.aligned.m16n8k16.row.col.f32.bf16.bf16.f32 "            \
        "{%0,%1,%2,%3}, {%4,%5,%6,%7}, {%8,%9}, {%0,%1,%2,%3};"           \
        : "+f"((d)[0]), "+f"((d)[1]), "+f"((d)[2]), "+f"((d)[3])           \
        : "r"((a)[0]), "r"((a)[1]), "r"((a)[2]), "r"((a)[3]),              \
          "r"(b0), "r"(b1))

#define LDM_X4(r, a)                                                       \
    asm volatile("ldmatrix.sync.aligned.m8n8.x4.shared.b16 "               \
                 "{%0,%1,%2,%3}, [%4];"                                    \
                 : "=r"((r)[0]), "=r"((r)[1]), "=r"((r)[2]), "=r"((r)[3])  \
                 : "r"(a))

#define CP16(d, s)                                                         \
    asm volatile("cp.async.cg.shared.global [%0], [%1], 16;"               \
                 :: "r"(d), "l"(s))
#define CP_COMMIT() asm volatile("cp.async.commit_group;" ::: "memory")
#define CP_WAIT0()  asm volatile("cp.async.wait_group 0;" ::: "memory")
#define CP_WAIT1()  asm volatile("cp.async.wait_group 1;" ::: "memory")

__device__ __forceinline__ uint32_t sptr(const void* p) {
    return (uint32_t)__cvta_generic_to_shared(p);
}

// ---------------------------------------------------------------------------
// fp32 -> (bf16 hi, bf16 lo) splits
// ---------------------------------------------------------------------------
__device__ __forceinline__ void split_store(__nv_bfloat16* hi, __nv_bfloat16* lo,
                                            int i, float4 v)
{
    uint32_t h0 = pack_bf16x2(v.x, v.y);
    uint32_t h1 = pack_bf16x2(v.z, v.w);
    float r0 = v.x - __uint_as_float(h0 << 16);
    float r1 = v.y - __uint_as_float(h0 & 0xffff0000u);
    float r2 = v.z - __uint_as_float(h1 << 16);
    float r3 = v.w - __uint_as_float(h1 & 0xffff0000u);
    ((uint32_t*)hi)[2 * i + 0] = h0;
    ((uint32_t*)hi)[2 * i + 1] = h1;
    ((uint32_t*)lo)[2 * i + 0] = pack_bf16x2(r0, r1);
    ((uint32_t*)lo)[2 * i + 1] = pack_bf16x2(r2, r3);
}

__global__ __launch_bounds__(256) void convert_x(const float* __restrict__ src, int n4)
{
    int i = blockIdx.x * blockDim.x + threadIdx.x;
    if (i >= n4) return;
    split_store(g_xhi, g_xlo, i, ((const float4*)src)[i]);
}

__global__ __launch_bounds__(256) void convert_w(const float* __restrict__ w0,
                                                 const float* __restrict__ w1,
                                                 const float* __restrict__ w2,
                                                 const float* __restrict__ w3,
                                                 int n4)
{
    int i = blockIdx.x * blockDim.x + threadIdx.x;
    if (i >= n4) return;
    int wi = blockIdx.y;
    const float* src = (wi == 0) ? w0 : (wi == 1) ? w1 : (wi == 2) ? w2 : w3;
    split_store(g_whi + (size_t)wi * EMB * EMB,
                g_wlo + (size_t)wi * EMB * EMB, i, ((const float4*)src)[i]);
}

// ---------------------------------------------------------------------------
// mma.sync bf16-split GEMM, 128x128 tiles, BK=32, 8 warps (4M x 2N),
// 2-stage cp.async pipeline. mode = base_mode + blockIdx.z.
// mode 0/1/2 -> q/k/v bf16 hi/lo [h][tok][64]; mode 3 -> fp32 outp [N][768].
// Dynamic smem: 2 bufs x (Ah,Al,Bh,Bl each 128x40 bf16 = 10240B) = 81920B.
// ---------------------------------------------------------------------------
#define G_ARR 10240
#define G_BUF 40960
#define G_SMEM 81920

__global__ __launch_bounds__(256) void gemm_tc(const float* __restrict__ b0,
                                               const float* __restrict__ b1,
                                               const float* __restrict__ b2,
                                               float* __restrict__ outp,
                                               int base_mode)
{
    extern __shared__ char smx[];
    uint32_t sb = sptr(smx);

    int mode = base_mode + blockIdx.z;
    const float* bias = (blockIdx.z == 0) ? b0 : (blockIdx.z == 1) ? b1 : b2;
    const __nv_bfloat16* wh = g_whi + (size_t)mode * EMB * EMB;
    const __nv_bfloat16* wl = g_wlo + (size_t)mode * EMB * EMB;

    int nb = blockIdx.x * 128, mb = blockIdx.y * 128;
    int tid = threadIdx.x, w = tid >> 5, lane = tid & 31;
    int qr = lane >> 2, qc = (lane & 3) * 2;
    int wm = w & 3, wn = w >> 2;

    // ldmatrix lane addressing (row stride 80 bytes)
    int a_r  = wm * 32 + (lane & 7) + ((lane >> 3) & 1) * 8;
    int a_cb = ((lane >> 4) & 1) * 16;
    int b_r  = wn * 64 + (lane & 7) + ((lane >> 4) & 1) * 8;
    int b_cb = ((lane >> 3) & 1) * 16;

    float acc[2][8][4];
    #pragma unroll
    for (int m = 0; m < 2; m++)
        #pragma unroll
        for (int n = 0; n < 8; n++)
            #pragma unroll
            for (int j = 0; j < 4; j++) acc[m][n][j] = 0.f;

    auto issue = [&](int kc) {
        uint32_t off = sb + (uint32_t)(kc & 1) * G_BUF;
        int ke = kc * 32;  // element offset in K
        #pragma unroll
        for (int i = 0; i < 2; i++) {
            int idx = tid + i * 256;
            int r = idx >> 2, cb = (idx & 3) * 16;
            uint32_t so = (uint32_t)(r * 80 + cb);
            CP16(off + so,              (const char*)(g_xhi + (size_t)(mb + r) * EMB + ke) + cb);
            CP16(off + G_ARR + so,      (const char*)(g_xlo + (size_t)(mb + r) * EMB + ke) + cb);
            CP16(off + 2 * G_ARR + so,  (const char*)(wh + (size_t)(nb + r) * EMB + ke) + cb);
            CP16(off + 3 * G_ARR + so,  (const char*)(wl + (size_t)(nb + r) * EMB + ke) + cb);
        }
        CP_COMMIT();
    };

    const int NC = EMB / 32;  // 24
    issue(0);

    for (int kc = 0; kc < NC; kc++) {
        if (kc + 1 < NC) { issue(kc + 1); CP_WAIT1(); }
        else             { CP_WAIT0(); }
        __syncthreads();

        uint32_t off = sb + (uint32_t)(kc & 1) * G_BUF;
        #pragma unroll
        for (int t = 0; t < 2; t++) {
            uint32_t ah[2][4], al[2][4];
            #pragma unroll
            for (int m = 0; m < 2; m++) {
                uint32_t ao = (uint32_t)((a_r + m * 16) * 80 + t * 32 + a_cb);
                LDM_X4(ah[m], off + ao);
                LDM_X4(al[m], off + G_ARR + ao);
            }
            #pragma unroll
            for (int nbk = 0; nbk < 4; nbk++) {
                uint32_t kh[4], kl[4];
                uint32_t bo = (uint32_t)((b_r + nbk * 16) * 80 + t * 32 + b_cb);
                LDM_X4(kh, off + 2 * G_ARR + bo);
                LDM_X4(kl, off + 3 * G_ARR + bo);
                #pragma unroll
                for (int m = 0; m < 2; m++) {
                    MMA_BF16(acc[m][2 * nbk], ah[m], kh[0], kh[1]);
                    MMA_BF16(acc[m][2 * nbk], ah[m], kl[0], kl[1]);
                    MMA_BF16(acc[m][2 * nbk], al[m], kh[0], kh[1]);
                    MMA_BF16(acc[m][2 * nbk + 1], ah[m], kh[2], kh[3]);
                    MMA_BF16(acc[m][2 * nbk + 1], ah[m], kl[2], kl[3]);
                    MMA_BF16(acc[m][2 * nbk + 1], al[m], kh[2], kh[3]);
                }
            }
        }
        __syncthreads();
    }

    #pragma unroll
    for (int m = 0; m < 2; m++) {
        int r0 = mb + wm * 32 + m * 16 + qr;
        if (mode == 3) {
            #pragma unroll
            for (int n = 0; n < 8; n++) {
                int col = nb + wn * 64 + n * 8 + qc;
                float2 v0 = {acc[m][n][0] + bias[col], acc[m][n][1] + bias[col + 1]};
                float2 v1 = {acc[m][n][2] + bias[col], acc[m][n][3] + bias[col + 1]};
                *(float2*)(outp + (size_t)r0 * EMB + col) = v0;
                *(float2*)(outp + (size_t)(r0 + 8) * EMB + col) = v1;
            }
        } else {
            __nv_bfloat16* dh = (mode == 0) ? g_qhi : (mode == 1) ? g_khi : g_vhi;
            __nv_bfloat16* dl = (mode == 0) ? g_qlo : (mode == 1) ? g_klo : g_vlo;
            int hh = blockIdx.x * 2 + wn;
            #pragma unroll
            for (int n = 0; n < 8; n++) {
                int d = n * 8 + qc;
                int col = nb + wn * 64 + d;
                float bb0 = bias[col], bb1 = bias[col + 1];
                #pragma unroll
                for (int half = 0; half < 2; half++) {
                    float v0 = acc[m][n][half * 2 + 0] + bb0;
                    float v1 = acc[m][n][half * 2 + 1] + bb1;
                    uint32_t ph = pack_bf16x2(v0, v1);
                    float e0 = v0 - __uint_as_float(ph << 16);
                    float e1 = v1 - __uint_as_float(ph & 0xffff0000u);
                    size_t offd = ((size_t)hh * NTOK + r0 + half * 8) * HD + d;
                    *(uint32_t*)(dh + offd) = ph;
                    *(uint32_t*)(dl + offd) = pack_bf16x2(e0, e1);
                }
            }
        }
    }
}

// ---------------------------------------------------------------------------
// V transpose: g_v{hi,lo} [h][tok][64] -> g_vt{hi,lo} [h][64][tok]
// ---------------------------------------------------------------------------
__global__ __launch_bounds__(256) void transpose_v()
{
    __shared__ __nv_bfloat16 th[64][PADB], tl[64][PADB];
    int h = blockIdx.y, j0 = blockIdx.x * 64, tid = threadIdx.x;

    for (int idx = tid; idx < 512; idx += 256) {
        int r = idx >> 3, c = idx & 7;
        const char* sh = (const char*)(g_vhi + ((size_t)h * NTOK + j0 + r) * HD) + c * 16;
        const char* sl = (const char*)(g_vlo + ((size_t)h * NTOK + j0 + r) * HD) + c * 16;
        *(uint4*)((char*)&th[r][0] + c * 16) = *(const uint4*)sh;
        *(uint4*)((char*)&tl[r][0] + c * 16) = *(const uint4*)sl;
    }
    __syncthreads();

    for (int odx = tid; odx < 2048; odx += 256) {
        int d = odx >> 5, tk = (odx & 31) * 2;
        uint32_t ph = ((uint32_t)__bfloat16_as_ushort(th[tk][d])) |
                      ((uint32_t)__bfloat16_as_ushort(th[tk + 1][d]) << 16);
        uint32_t pl = ((uint32_t)__bfloat16_as_ushort(tl[tk][d])) |
                      ((uint32_t)__bfloat16_as_ushort(tl[tk + 1][d]) << 16);
        size_t off = ((size_t)h * HD + d) * NTOK + j0 + tk;
        *(uint32_t*)(g_vthi + off) = ph;
        *(uint32_t*)(g_vtlo + off) = pl;
    }
}

// ---------------------------------------------------------------------------
// Tensor-core flash attention. Block = 128 queries x 1 head, 8 warps,
// 2-stage cp.async pipeline on K/V tiles. Output fused into bf16-split
// g_xhi/g_xlo (input of the O-projection).
// Dynamic smem: 2 bufs x (Kh,Kl,Vh,Vl each 64x72 bf16 = 9216B) = 73728
//   + bc 128x64 u8 (8192) + sims 1280 ints (5120) = 87040B.
// ---------------------------------------------------------------------------
#define A_TL  9216
#define A_BUF 36864
#define A_BC  73728
#define A_SIM 81920
#define A_SMEM 87040
#define QB 128

__global__ __launch_bounds__(256) void attn_tc(const int* __restrict__ sim)
{
    extern __shared__ char smx[];
    uint32_t sb = sptr(smx);
    unsigned char (*bc)[64] = (unsigned char (*)[64])(smx + A_BC);
    int* sims = (int*)(smx + A_SIM);

    int h = blockIdx.y, i0 = blockIdx.x * QB;
    int tid = threadIdx.x, w = tid >> 5, lane = tid & 31;
    int qr = lane >> 2, qc = (lane & 3) * 2;

    for (int t = tid; t < QB * 10; t += 256) sims[t] = sim[(size_t)i0 * 10 + t];

    // Persistent Q fragments
    uint32_t qh[4][4], ql[4][4];
    {
        const __nv_bfloat16* qbh = g_qhi + ((size_t)h * NTOK + i0 + w * 16) * HD;
        const __nv_bfloat16* qbl = g_qlo + ((size_t)h * NTOK + i0 + w * 16) * HD;
        #pragma unroll
        for (int t = 0; t < 4; t++)
            #pragma unroll
            for (int j = 0; j < 4; j++) {
                int r = qr + (j & 1) * 8;
                int c = t * 16 + qc + (j >> 1) * 8;
                qh[t][j] = *(const uint32_t*)(qbh + (size_t)r * HD + c);
                ql[t][j] = *(const uint32_t*)(qbl + (size_t)r * HD + c);
            }
    }

    const __nv_bfloat16* kbh = g_khi + (size_t)h * NTOK * HD;
    const __nv_bfloat16* kbl = g_klo + (size_t)h * NTOK * HD;
    const __nv_bfloat16* vbh = g_vthi + (size_t)h * HD * NTOK;
    const __nv_bfloat16* vbl = g_vtlo + (size_t)h * HD * NTOK;

    int b_rl = (lane & 7) + ((lane >> 4) & 1) * 8;
    int b_cb = ((lane >> 3) & 1) * 16;

    auto issue = [&](int kt) {
        uint32_t off = sb + (uint32_t)(kt & 1) * A_BUF;
        int j0 = kt * 64;
        #pragma unroll
        for (int i = 0; i < 2; i++) {
            int idx = tid + i * 256;
            int r = idx >> 3, cb = (idx & 7) * 16;
            uint32_t so = (uint32_t)(r * (PADB * 2) + cb);
            CP16(off + so,             (const char*)(kbh + (size_t)(j0 + r) * HD) + cb);
            CP16(off + A_TL + so,      (const char*)(kbl + (size_t)(j0 + r) * HD) + cb);
            CP16(off + 2 * A_TL + so,  (const char*)(vbh + (size_t)r * NTOK + j0) + cb);
            CP16(off + 3 * A_TL + so,  (const char*)(vbl + (size_t)r * NTOK + j0) + cb);
        }
        CP_COMMIT();
    };

    float o[8][4];
    #pragma unroll
    for (int n = 0; n < 8; n++)
        #pragma unroll
        for (int j = 0; j < 4; j++) o[n][j] = 0.f;
    float m0 = -1e30f, m1 = -1e30f, l0 = 0.f, l1 = 0.f;
    int br0 = w * 16 + qr, br1 = br0 + 8;

    const int NT = NTOK / 64;  // 64
    issue(0);

    for (int kt = 0; kt < NT; kt++) {
        int j0 = kt * 64;
        if (kt + 1 < NT) issue(kt + 1);

        // zero bias counts (previous compute finished at loop-end sync)
        for (int idx = tid; idx < 512; idx += 256)
            ((uint4*)bc)[idx] = make_uint4(0u, 0u, 0u, 0u);
        __syncthreads();
        if (tid < QB) {
            #pragma unroll
            for (int s5 = 0; s5 < 10; s5++) {
                int rel = sims[tid * 10 + s5] - j0;
                if ((unsigned)rel < 64u) bc[tid][rel]++;
            }
        }
        if (kt + 1 < NT) { CP_WAIT1(); } else { CP_WAIT0(); }
        __syncthreads();

        uint32_t off = sb + (uint32_t)(kt & 1) * A_BUF;
        uint32_t sKh = off, sKl = off + A_TL, sVh = off + 2 * A_TL, sVl = off + 3 * A_TL;

        // ---- S = Q K^T (3-pass bf16 split) ----
        float s[8][4];
        #pragma unroll
        for (int n = 0; n < 8; n++)
            #pragma unroll
            for (int j = 0; j < 4; j++) s[n][j] = 0.f;
        #pragma unroll
        for (int t = 0; t < 4; t++) {
            #pragma unroll
            for (int nbk = 0; nbk < 4; nbk++) {
                uint32_t kh[4], kl[4];
                uint32_t boff = (uint32_t)((nbk * 16 + b_rl) * (PADB * 2) + t * 32 + b_cb);
                LDM_X4(kh, sKh + boff);
                LDM_X4(kl, sKl + boff);
                MMA_BF16(s[2 * nbk], qh[t], kh[0], kh[1]);
                MMA_BF16(s[2 * nbk], qh[t], kl[0], kl[1]);
                MMA_BF16(s[2 * nbk], ql[t], kh[0], kh[1]);
                MMA_BF16(s[2 * nbk + 1], qh[t], kh[2], kh[3]);
                MMA_BF16(s[2 * nbk + 1], qh[t], kl[2], kl[3]);
                MMA_BF16(s[2 * nbk + 1], ql[t], kh[2], kh[3]);
            }
        }

        // ---- scale + bias + online softmax ----
        float mx0 = -1e30f, mx1 = -1e30f;
        #pragma unroll
        for (int n = 0; n < 8; n++) {
            int c0i = n * 8 + qc;
            s[n][0] = fmaf(s[n][0], 0.125f, (float)bc[br0][c0i]);
            s[n][1] = fmaf(s[n][1], 0.125f, (float)bc[br0][c0i + 1]);
            s[n][2] = fmaf(s[n][2], 0.125f, (float)bc[br1][c0i]);
            s[n][3] = fmaf(s[n][3], 0.125f, (float)bc[br1][c0i + 1]);
            mx0 = fmaxf(mx0, fmaxf(s[n][0], s[n][1]));
            mx1 = fmaxf(mx1, fmaxf(s[n][2], s[n][3]));
        }
        #pragma unroll
        for (int off2 = 1; off2 <= 2; off2 <<= 1) {
            mx0 = fmaxf(mx0, __shfl_xor_sync(0xffffffffu, mx0, off2));
            mx1 = fmaxf(mx1, __shfl_xor_sync(0xffffffffu, mx1, off2));
        }
        float mn0 = fmaxf(m0, mx0), mn1 = fmaxf(m1, mx1);
        float a0 = exp2p((m0 - mn0) * L2E), a1 = exp2p((m1 - mn1) * L2E);

        float rs0 = 0.f, rs1 = 0.f;
        uint32_t pa[4][4], pl[4][4];
        #pragma unroll
        for (int n = 0; n < 8; n++) {
            float p0 = exp2p((s[n][0] - mn0) * L2E);
            float p1 = exp2p((s[n][1] - mn0) * L2E);
            float p2 = exp2p((s[n][2] - mn1) * L2E);
            float p3 = exp2p((s[n][3] - mn1) * L2E);
            rs0 += p0 + p1;
            rs1 += p2 + p3;
            uint32_t hp01 = pack_bf16x2(p0, p1);
            uint32_t hp23 = pack_bf16x2(p2, p3);
            float e0 = p0 - __uint_as_float(hp01 << 16);
            float e1 = p1 - __uint_as_float(hp01 & 0xffff0000u);
            float e2 = p2 - __uint_as_float(hp23 << 16);
            float e3 = p3 - __uint_as_float(hp23 & 0xffff0000u);
            int t = n >> 1, half = (n & 1) * 2;
            pa[t][half + 0] = hp01;
            pa[t][half + 1] = hp23;
            pl[t][half + 0] = pack_bf16x2(e0, e1);
            pl[t][half + 1] = pack_bf16x2(e2, e3);
        }
        #pragma unroll
        for (int off2 = 1; off2 <= 2; off2 <<= 1) {
            rs0 += __shfl_xor_sync(0xffffffffu, rs0, off2);
            rs1 += __shfl_xor_sync(0xffffffffu, rs1, off2);
        }
        l0 = l0 * a0 + rs0;
        l1 = l1 * a1 + rs1;
        m0 = mn0;
        m1 = mn1;
        #pragma unroll
        for (int n = 0; n < 8; n++) {
            o[n][0] *= a0; o[n][1] *= a0;
            o[n][2] *= a1; o[n][3] *= a1;
        }

        // ---- O += P V (3-pass bf16 split) ----
        #pragma unroll
        for (int t = 0; t < 4; t++) {
            #pragma unroll
            for (int nbk = 0; nbk < 4; nbk++) {
                uint32_t vh[4], vl[4];
                uint32_t boff = (uint32_t)((nbk * 16 + b_rl) * (PADB * 2) + t * 32 + b_cb);
                LDM_X4(vh, sVh + boff);
                LDM_X4(vl, sVl + boff);
                MMA_BF16(o[2 * nbk], pa[t], vh[0], vh[1]);
                MMA_BF16(o[2 * nbk], pa[t], vl[0], vl[1]);
                MMA_BF16(o[2 * nbk], pl[t], vh[0], vh[1]);
                MMA_BF16(o[2 * nbk + 1], pa[t], vh[2], vh[3]);
                MMA_BF16(o[2 * nbk + 1], pa[t], vl[2], vl[3]);
                MMA_BF16(o[2 * nbk + 1], pl[t], vh[2], vh[3]);
            }
        }
        __syncthreads();
    }

    // Fused epilogue: split-store O directly as O-projection input
    float il0 = 1.f / l0, il1 = 1.f / l1;
    #pragma unroll
    for (int n = 0; n < 8; n++) {
        int col = h * HD + n * 8 + qc;
        float v0 = o[n][0] * il0, v1 = o[n][1] * il0;
        float v2 = o[n][2] * il1, v3 = o[n][3] * il1;
        uint32_t h0 = pack_bf16x2(v0, v1);
        uint32_t h1 = pack_bf16x2(v2, v3);
        float e0 = v0 - __uint_as_float(h0 << 16);
        float e1 = v1 - __uint_as_float(h0 & 0xffff0000u);
        float e2 = v2 - __uint_as_float(h1 << 16);
        float e3 = v3 - __uint_as_float(h1 & 0xffff0000u);
        size_t o0 = (size_t)(i0 + br0) * EMB + col;
        size_t o1 = (size_t)(i0 + br1) * EMB + col;
        *(uint32_t*)(g_xhi + o0) = h0;
        *(uint32_t*)(g_xlo + o0) = pack_bf16x2(e0, e1);
        *(uint32_t*)(g_xhi + o1) = h1;
        *(uint32_t*)(g_xlo + o1) = pack_bf16x2(e2, e3);
    }
}

// ---------------------------------------------------------------------------
extern "C" void kernel_launch(void* const* d_in, const int* in_sizes, int n_in,
                              void* d_out, int out_size)
{
    const float* x   = (const float*)d_in[0];
    const int*   sim = (const int*)d_in[1];
    const float* Wq  = (const float*)d_in[2];
    const float* bq  = (const float*)d_in[3];
    const float* Wk  = (const float*)d_in[4];
    const float* bk  = (const float*)d_in[5];
    const float* Wv  = (const float*)d_in[6];
    const float* bv  = (const float*)d_in[7];
    const float* Wo  = (const float*)d_in[8];
    const float* bo  = (const float*)d_in[9];
    float* out = (float*)d_out;

    cudaFuncSetAttribute(gemm_tc, cudaFuncAttributeMaxDynamicSharedMemorySize, G_SMEM);
    cudaFuncSetAttribute(attn_tc, cudaFuncAttributeMaxDynamicSharedMemorySize, A_SMEM);

    const int n4x = NTOK * EMB / 4;
    const int n4w = EMB * EMB / 4;

    convert_x<<<n4x / 256, 256>>>(x, n4x);
    convert_w<<<dim3(n4w / 256, 4), 256>>>(Wq, Wk, Wv, Wo, n4w);

    gemm_tc<<<dim3(EMB / 128, NTOK / 128, 3), 256, G_SMEM>>>(bq, bk, bv, nullptr, 0);

    transpose_v<<<dim3(NTOK / 64, NH), 256>>>();
    attn_tc<<<dim3(NTOK / QB, NH), 256, A_SMEM>>>(sim);

    gemm_tc<<<dim3(EMB / 128, NTOK / 128, 1), 256, G_SMEM>>>(bo, nullptr, nullptr, out, 3);
}

// round 10
// speedup vs baseline: 1.1359x; 1.1359x over previous
#include <cuda_runtime.h>
#include <cuda_bf16.h>
#include <cstdint>

#define NTOK 4096
#define EMB  768
#define NH   12
#define HD   64
#define PADB 72
#define L2E  1.4426950408889634f

// ---------------------------------------------------------------------------
// Scratch (allocation-free device globals)
// ---------------------------------------------------------------------------
__device__ __align__(16) __nv_bfloat16 g_xhi[NTOK * EMB];
__device__ __align__(16) __nv_bfloat16 g_xlo[NTOK * EMB];
__device__ __align__(16) __nv_bfloat16 g_whi[4 * EMB * EMB];
__device__ __align__(16) __nv_bfloat16 g_wlo[4 * EMB * EMB];
__device__ __align__(16) __nv_bfloat16 g_qhi[NH * NTOK * HD];
__device__ __align__(16) __nv_bfloat16 g_qlo[NH * NTOK * HD];
__device__ __align__(16) __nv_bfloat16 g_khi[NH * NTOK * HD];
__device__ __align__(16) __nv_bfloat16 g_klo[NH * NTOK * HD];
__device__ __align__(16) __nv_bfloat16 g_vthi[NH * HD * NTOK];
__device__ __align__(16) __nv_bfloat16 g_vtlo[NH * HD * NTOK];

// ---------------------------------------------------------------------------
// Helpers
// ---------------------------------------------------------------------------
__device__ __forceinline__ uint32_t pack_bf16x2(float lo, float hi) {
    uint32_t r;
    asm("cvt.rn.bf16x2.f32 %0, %1, %2;" : "=r"(r) : "f"(hi), "f"(lo));
    return r;
}

// fast exp2 on the FMA pipe, input <= 0
__device__ __forceinline__ float exp2p(float t) {
    t = fmaxf(t, -120.f);
    float z  = t + 12582912.f;            // 1.5 * 2^23
    float fi = z - 12582912.f;
    float f  = t - fi;
    float p = fmaf(0.00133335581f, f, 0.00961812911f);
    p = fmaf(p, f, 0.0555041087f);
    p = fmaf(p, f, 0.240226507f);
    p = fmaf(p, f, 0.69314718056f);
    p = fmaf(p, f, 1.0f);
    return p * __int_as_float((__float_as_int(z) + 127) << 23);
}

#define MMA_BF16(d, a, b0, b1)                                             \
    asm volatile(                                                          \
        "mma.sync.aligned.m16n8k16.row.col.f32.bf16.bf16.f32 "            \
        "{%0,%1,%2,%3}, {%4,%5,%6,%7}, {%8,%9}, {%0,%1,%2,%3};"           \
        : "+f"((d)[0]), "+f"((d)[1]), "+f"((d)[2]), "+f"((d)[3])           \
        : "r"((a)[0]), "r"((a)[1]), "r"((a)[2]), "r"((a)[3]),              \
          "r"(b0), "r"(b1))

#define LDM_X4(r, a)                                                       \
    asm volatile("ldmatrix.sync.aligned.m8n8.x4.shared.b16 "               \
                 "{%0,%1,%2,%3}, [%4];"                                    \
                 : "=r"((r)[0]), "=r"((r)[1]), "=r"((r)[2]), "=r"((r)[3])  \
                 : "r"(a))

#define CP16(d, s)                                                         \
    asm volatile("cp.async.cg.shared.global [%0], [%1], 16;"               \
                 :: "r"(d), "l"(s))
#define CP_COMMIT() asm volatile("cp.async.commit_group;" ::: "memory")
#define CP_WAIT0()  asm volatile("cp.async.wait_group 0;" ::: "memory")

__device__ __forceinline__ uint32_t sptr(const void* p) {
    return (uint32_t)__cvta_generic_to_shared(p);
}

// ---------------------------------------------------------------------------
// fp32 -> (bf16 hi, bf16 lo) splits
// ---------------------------------------------------------------------------
__device__ __forceinline__ void split_store(__nv_bfloat16* hi, __nv_bfloat16* lo,
                                            int i, float4 v)
{
    uint32_t h0 = pack_bf16x2(v.x, v.y);
    uint32_t h1 = pack_bf16x2(v.z, v.w);
    float r0 = v.x - __uint_as_float(h0 << 16);
    float r1 = v.y - __uint_as_float(h0 & 0xffff0000u);
    float r2 = v.z - __uint_as_float(h1 << 16);
    float r3 = v.w - __uint_as_float(h1 & 0xffff0000u);
    ((uint32_t*)hi)[2 * i + 0] = h0;
    ((uint32_t*)hi)[2 * i + 1] = h1;
    ((uint32_t*)lo)[2 * i + 0] = pack_bf16x2(r0, r1);
    ((uint32_t*)lo)[2 * i + 1] = pack_bf16x2(r2, r3);
}

__global__ __launch_bounds__(256) void convert_x(const float* __restrict__ src, int n4)
{
    int i = blockIdx.x * blockDim.x + threadIdx.x;
    if (i >= n4) return;
    split_store(g_xhi, g_xlo, i, ((const float4*)src)[i]);
}

__global__ __launch_bounds__(256) void convert_w(const float* __restrict__ w0,
                                                 const float* __restrict__ w1,
                                                 const float* __restrict__ w2,
                                                 const float* __restrict__ w3,
                                                 int n4)
{
    int i = blockIdx.x * blockDim.x + threadIdx.x;
    if (i >= n4) return;
    int wi = blockIdx.y;
    const float* src = (wi == 0) ? w0 : (wi == 1) ? w1 : (wi == 2) ? w2 : w3;
    split_store(g_whi + (size_t)wi * EMB * EMB,
                g_wlo + (size_t)wi * EMB * EMB, i, ((const float4*)src)[i]);
}

// ---------------------------------------------------------------------------
// mma.sync bf16-split GEMM: C = A(4096x768) @ W^T + bias.
// mode = base_mode + blockIdx.z. mode 0/1 -> q/k bf16 hi/lo [h][tok][64];
// mode 2 -> v bf16 hi/lo TRANSPOSED [h][d][tok]; mode 3 -> fp32 outp [N][768].
// Block 64(M) x 64(N), 4 warps. ldmatrix fragments, cp.async loads.
// ---------------------------------------------------------------------------
__global__ __launch_bounds__(128) void gemm_tc(const float* __restrict__ b0,
                                               const float* __restrict__ b1,
                                               const float* __restrict__ b2,
                                               float* __restrict__ outp,
                                               int base_mode)
{
    __shared__ __nv_bfloat16 Ah[64][PADB], Al[64][PADB];
    __shared__ __nv_bfloat16 Bh[64][PADB], Bl[64][PADB];

    int mode = base_mode + blockIdx.z;
    const float* bias = (blockIdx.z == 0) ? b0 : (blockIdx.z == 1) ? b1 : b2;
    const __nv_bfloat16* wh = g_whi + (size_t)mode * EMB * EMB;
    const __nv_bfloat16* wl = g_wlo + (size_t)mode * EMB * EMB;

    int nb = blockIdx.x * 64, mb = blockIdx.y * 64;
    int tid = threadIdx.x, w = tid >> 5, lane = tid & 31;
    int qr = lane >> 2, qc = (lane & 3) * 2;

    uint32_t sAh = sptr(&Ah[0][0]), sAl = sptr(&Al[0][0]);
    uint32_t sBh = sptr(&Bh[0][0]), sBl = sptr(&Bl[0][0]);

    // ldmatrix lane addressing
    int a_r = w * 16 + (lane & 7) + ((lane >> 3) & 1) * 8;
    int a_cb = ((lane >> 4) & 1) * 16;                   // byte offset of k-half
    int b_rl = (lane & 7) + ((lane >> 4) & 1) * 8;       // row within 16-n block
    int b_cb = ((lane >> 3) & 1) * 16;

    float acc[8][4];
    #pragma unroll
    for (int n = 0; n < 8; n++)
        #pragma unroll
        for (int j = 0; j < 4; j++) acc[n][j] = 0.f;

    for (int kc = 0; kc < EMB / 64; kc++) {
        __syncthreads();
        #pragma unroll
        for (int i = 0; i < 4; i++) {
            int idx = tid + i * 128;
            int r = idx >> 3, cb = (idx & 7) * 16;
            const char* ga = (const char*)(g_xhi + (size_t)(mb + r) * EMB + kc * 64) + cb;
            const char* gal = (const char*)(g_xlo + (size_t)(mb + r) * EMB + kc * 64) + cb;
            const char* gb = (const char*)(wh + (size_t)(nb + r) * EMB + kc * 64) + cb;
            const char* gbl = (const char*)(wl + (size_t)(nb + r) * EMB + kc * 64) + cb;
            uint32_t so = (uint32_t)(r * (PADB * 2) + cb);
            CP16(sAh + so, ga);
            CP16(sAl + so, gal);
            CP16(sBh + so, gb);
            CP16(sBl + so, gbl);
        }
        CP_COMMIT();
        CP_WAIT0();
        __syncthreads();

        #pragma unroll
        for (int t = 0; t < 4; t++) {
            uint32_t ah[4], al[4];
            uint32_t aoff = (uint32_t)(a_r * (PADB * 2) + t * 32 + a_cb);
            LDM_X4(ah, sAh + aoff);
            LDM_X4(al, sAl + aoff);
            #pragma unroll
            for (int nbk = 0; nbk < 4; nbk++) {
                uint32_t kh[4], kl[4];
                uint32_t boff = (uint32_t)((nbk * 16 + b_rl) * (PADB * 2) + t * 32 + b_cb);
                LDM_X4(kh, sBh + boff);
                LDM_X4(kl, sBl + boff);
                MMA_BF16(acc[2 * nbk], ah, kh[0], kh[1]);
                MMA_BF16(acc[2 * nbk], ah, kl[0], kl[1]);
                MMA_BF16(acc[2 * nbk], al, kh[0], kh[1]);
                MMA_BF16(acc[2 * nbk + 1], ah, kh[2], kh[3]);
                MMA_BF16(acc[2 * nbk + 1], ah, kl[2], kl[3]);
                MMA_BF16(acc[2 * nbk + 1], al, kh[2], kh[3]);
            }
        }
    }

    int r0 = mb + w * 16 + qr;
    if (mode == 3) {
        #pragma unroll
        for (int n = 0; n < 8; n++) {
            int col = nb + n * 8 + qc;
            float2 v0 = {acc[n][0] + bias[col], acc[n][1] + bias[col + 1]};
            float2 v1 = {acc[n][2] + bias[col], acc[n][3] + bias[col + 1]};
            *(float2*)(outp + (size_t)r0 * EMB + col) = v0;
            *(float2*)(outp + (size_t)(r0 + 8) * EMB + col) = v1;
        }
    } else if (mode == 2) {
        // V: write bf16 hi/lo directly TRANSPOSED into g_vt [h][d][tok]
        int hh = blockIdx.x;
        #pragma unroll
        for (int n = 0; n < 8; n++) {
            int d = n * 8 + qc;
            float bb0 = bias[nb + d], bb1 = bias[nb + d + 1];
            #pragma unroll
            for (int half = 0; half < 2; half++) {
                float v0 = acc[n][half * 2 + 0] + bb0;
                float v1 = acc[n][half * 2 + 1] + bb1;
                int tok = r0 + half * 8;
                uint32_t ph = pack_bf16x2(v0, v1);
                float e0 = v0 - __uint_as_float(ph << 16);
                float e1 = v1 - __uint_as_float(ph & 0xffff0000u);
                uint32_t pe = pack_bf16x2(e0, e1);
                size_t o0 = ((size_t)hh * HD + d) * NTOK + tok;
                size_t o1 = ((size_t)hh * HD + d + 1) * NTOK + tok;
                g_vthi[o0] = __ushort_as_bfloat16((unsigned short)(ph & 0xffffu));
                g_vthi[o1] = __ushort_as_bfloat16((unsigned short)(ph >> 16));
                g_vtlo[o0] = __ushort_as_bfloat16((unsigned short)(pe & 0xffffu));
                g_vtlo[o1] = __ushort_as_bfloat16((unsigned short)(pe >> 16));
            }
        }
    } else {
        __nv_bfloat16* dh = (mode == 0) ? g_qhi : g_khi;
        __nv_bfloat16* dl = (mode == 0) ? g_qlo : g_klo;
        int hh = blockIdx.x;
        #pragma unroll
        for (int n = 0; n < 8; n++) {
            int d = n * 8 + qc;
            float bb0 = bias[nb + d], bb1 = bias[nb + d + 1];
            #pragma unroll
            for (int half = 0; half < 2; half++) {
                float v0 = acc[n][half * 2 + 0] + bb0;
                float v1 = acc[n][half * 2 + 1] + bb1;
                uint32_t ph = pack_bf16x2(v0, v1);
                float e0 = v0 - __uint_as_float(ph << 16);
                float e1 = v1 - __uint_as_float(ph & 0xffff0000u);
                size_t off = ((size_t)hh * NTOK + r0 + half * 8) * HD + d;
                *(uint32_t*)(dh + off) = ph;
                *(uint32_t*)(dl + off) = pack_bf16x2(e0, e1);
            }
        }
    }
}

// ---------------------------------------------------------------------------
// Tensor-core flash attention. Block = 64 queries x 1 head, 4 warps.
// ldmatrix B-fragments, cp.async tile loads, poly-exp2 softmax,
// sparse bias via per-tile u8 count scatter. Output fused into bf16-split
// g_xhi/g_xlo (the O-projection input).
// ---------------------------------------------------------------------------
__global__ __launch_bounds__(128) void attn_tc(const int* __restrict__ sim)
{
    __shared__ __nv_bfloat16 Kh[64][PADB], Kl[64][PADB];
    __shared__ __nv_bfloat16 Vh[64][PADB], Vl[64][PADB];   // [d][tok]
    __shared__ __align__(16) unsigned char bc[64][64];
    __shared__ int sims[640];

    int h = blockIdx.y, i0 = blockIdx.x * 64;
    int tid = threadIdx.x, w = tid >> 5, lane = tid & 31;
    int qr = lane >> 2, qc = (lane & 3) * 2;

    for (int t = tid; t < 640; t += 128) sims[t] = sim[(size_t)i0 * 10 + t];

    // Persistent Q fragments from global
    uint32_t qh[4][4], ql[4][4];
    {
        const __nv_bfloat16* qbh = g_qhi + ((size_t)h * NTOK + i0 + w * 16) * HD;
        const __nv_bfloat16* qbl = g_qlo + ((size_t)h * NTOK + i0 + w * 16) * HD;
        #pragma unroll
        for (int t = 0; t < 4; t++)
            #pragma unroll
            for (int j = 0; j < 4; j++) {
                int r = qr + (j & 1) * 8;
                int c = t * 16 + qc + (j >> 1) * 8;
                qh[t][j] = *(const uint32_t*)(qbh + (size_t)r * HD + c);
                ql[t][j] = *(const uint32_t*)(qbl + (size_t)r * HD + c);
            }
    }

    const __nv_bfloat16* kbh = g_khi + (size_t)h * NTOK * HD;
    const __nv_bfloat16* kbl = g_klo + (size_t)h * NTOK * HD;
    const __nv_bfloat16* vbh = g_vthi + (size_t)h * HD * NTOK;
    const __nv_bfloat16* vbl = g_vtlo + (size_t)h * HD * NTOK;

    uint32_t sKh = sptr(&Kh[0][0]), sKl = sptr(&Kl[0][0]);
    uint32_t sVh = sptr(&Vh[0][0]), sVl = sptr(&Vl[0][0]);

    int b_rl = (lane & 7) + ((lane >> 4) & 1) * 8;
    int b_cb = ((lane >> 3) & 1) * 16;

    float o[8][4];
    #pragma unroll
    for (int n = 0; n < 8; n++)
        #pragma unroll
        for (int j = 0; j < 4; j++) o[n][j] = 0.f;
    float m0 = -1e30f, m1 = -1e30f, l0 = 0.f, l1 = 0.f;
    int br0 = w * 16 + qr, br1 = br0 + 8;

    for (int kt = 0; kt < NTOK / 64; kt++) {
        int j0 = kt * 64;
        __syncthreads();
        #pragma unroll
        for (int i = 0; i < 4; i++) {
            int idx = tid + i * 128;
            int r = idx >> 3, cb = (idx & 7) * 16;
            uint32_t so = (uint32_t)(r * (PADB * 2) + cb);
            CP16(sKh + so, (const char*)(kbh + (size_t)(j0 + r) * HD) + cb);
            CP16(sKl + so, (const char*)(kbl + (size_t)(j0 + r) * HD) + cb);
            CP16(sVh + so, (const char*)(vbh + (size_t)r * NTOK + j0) + cb);
            CP16(sVl + so, (const char*)(vbl + (size_t)r * NTOK + j0) + cb);
        }
        CP_COMMIT();
        for (int idx = tid; idx < 256; idx += 128)
            *(uint4*)(&bc[0][0] + idx * 16) = make_uint4(0u, 0u, 0u, 0u);
        CP_WAIT0();
        __syncthreads();
        if (tid < 64) {
            #pragma unroll
            for (int s5 = 0; s5 < 10; s5++) {
                int rel = sims[tid * 10 + s5] - j0;
                if ((unsigned)rel < 64u) bc[tid][rel]++;
            }
        }
        __syncthreads();

        // ---- S = Q K^T (3-pass bf16 split) ----
        float s[8][4];
        #pragma unroll
        for (int n = 0; n < 8; n++)
            #pragma unroll
            for (int j = 0; j < 4; j++) s[n][j] = 0.f;
        #pragma unroll
        for (int t = 0; t < 4; t++) {
            #pragma unroll
            for (int nbk = 0; nbk < 4; nbk++) {
                uint32_t kh[4], kl[4];
                uint32_t boff = (uint32_t)((nbk * 16 + b_rl) * (PADB * 2) + t * 32 + b_cb);
                LDM_X4(kh, sKh + boff);
                LDM_X4(kl, sKl + boff);
                MMA_BF16(s[2 * nbk], qh[t], kh[0], kh[1]);
                MMA_BF16(s[2 * nbk], qh[t], kl[0], kl[1]);
                MMA_BF16(s[2 * nbk], ql[t], kh[0], kh[1]);
                MMA_BF16(s[2 * nbk + 1], qh[t], kh[2], kh[3]);
                MMA_BF16(s[2 * nbk + 1], qh[t], kl[2], kl[3]);
                MMA_BF16(s[2 * nbk + 1], ql[t], kh[2], kh[3]);
            }
        }

        // ---- scale + bias + online softmax ----
        float mx0 = -1e30f, mx1 = -1e30f;
        #pragma unroll
        for (int n = 0; n < 8; n++) {
            int c0i = n * 8 + qc;
            s[n][0] = fmaf(s[n][0], 0.125f, (float)bc[br0][c0i]);
            s[n][1] = fmaf(s[n][1], 0.125f, (float)bc[br0][c0i + 1]);
            s[n][2] = fmaf(s[n][2], 0.125f, (float)bc[br1][c0i]);
            s[n][3] = fmaf(s[n][3], 0.125f, (float)bc[br1][c0i + 1]);
            mx0 = fmaxf(mx0, fmaxf(s[n][0], s[n][1]));
            mx1 = fmaxf(mx1, fmaxf(s[n][2], s[n][3]));
        }
        #pragma unroll
        for (int off = 1; off <= 2; off <<= 1) {
            mx0 = fmaxf(mx0, __shfl_xor_sync(0xffffffffu, mx0, off));
            mx1 = fmaxf(mx1, __shfl_xor_sync(0xffffffffu, mx1, off));
        }
        float mn0 = fmaxf(m0, mx0), mn1 = fmaxf(m1, mx1);
        float a0 = exp2p((m0 - mn0) * L2E), a1 = exp2p((m1 - mn1) * L2E);

        float rs0 = 0.f, rs1 = 0.f;
        uint32_t pa[4][4], pl[4][4];
        #pragma unroll
        for (int n = 0; n < 8; n++) {
            float p0 = exp2p((s[n][0] - mn0) * L2E);
            float p1 = exp2p((s[n][1] - mn0) * L2E);
            float p2 = exp2p((s[n][2] - mn1) * L2E);
            float p3 = exp2p((s[n][3] - mn1) * L2E);
            rs0 += p0 + p1;
            rs1 += p2 + p3;
            uint32_t hp01 = pack_bf16x2(p0, p1);
            uint32_t hp23 = pack_bf16x2(p2, p3);
            float e0 = p0 - __uint_as_float(hp01 << 16);
            float e1 = p1 - __uint_as_float(hp01 & 0xffff0000u);
            float e2 = p2 - __uint_as_float(hp23 << 16);
            float e3 = p3 - __uint_as_float(hp23 & 0xffff0000u);
            int t = n >> 1, half = (n & 1) * 2;
            pa[t][half + 0] = hp01;
            pa[t][half + 1] = hp23;
            pl[t][half + 0] = pack_bf16x2(e0, e1);
            pl[t][half + 1] = pack_bf16x2(e2, e3);
        }
        #pragma unroll
        for (int off = 1; off <= 2; off <<= 1) {
            rs0 += __shfl_xor_sync(0xffffffffu, rs0, off);
            rs1 += __shfl_xor_sync(0xffffffffu, rs1, off);
        }
        l0 = l0 * a0 + rs0;
        l1 = l1 * a1 + rs1;
        m0 = mn0;
        m1 = mn1;
        #pragma unroll
        for (int n = 0; n < 8; n++) {
            o[n][0] *= a0; o[n][1] *= a0;
            o[n][2] *= a1; o[n][3] *= a1;
        }

        // ---- O += P V (3-pass bf16 split) ----
        #pragma unroll
        for (int t = 0; t < 4; t++) {
            #pragma unroll
            for (int nbk = 0; nbk < 4; nbk++) {
                uint32_t vh[4], vl[4];
                uint32_t boff = (uint32_t)((nbk * 16 + b_rl) * (PADB * 2) + t * 32 + b_cb);
                LDM_X4(vh, sVh + boff);
                LDM_X4(vl, sVl + boff);
                MMA_BF16(o[2 * nbk], pa[t], vh[0], vh[1]);
                MMA_BF16(o[2 * nbk], pa[t], vl[0], vl[1]);
                MMA_BF16(o[2 * nbk], pl[t], vh[0], vh[1]);
                MMA_BF16(o[2 * nbk + 1], pa[t], vh[2], vh[3]);
                MMA_BF16(o[2 * nbk + 1], pa[t], vl[2], vl[3]);
                MMA_BF16(o[2 * nbk + 1], pl[t], vh[2], vh[3]);
            }
        }
    }

    // Fused epilogue: split-store O directly as O-projection input
    float il0 = 1.f / l0, il1 = 1.f / l1;
    #pragma unroll
    for (int n = 0; n < 8; n++) {
        int col = h * HD + n * 8 + qc;
        float v0 = o[n][0] * il0, v1 = o[n][1] * il0;
        float v2 = o[n][2] * il1, v3 = o[n][3] * il1;
        uint32_t h0 = pack_bf16x2(v0, v1);
        uint32_t h1 = pack_bf16x2(v2, v3);
        float e0 = v0 - __uint_as_float(h0 << 16);
        float e1 = v1 - __uint_as_float(h0 & 0xffff0000u);
        float e2 = v2 - __uint_as_float(h1 << 16);
        float e3 = v3 - __uint_as_float(h1 & 0xffff0000u);
        size_t o0 = (size_t)(i0 + br0) * EMB + col;
        size_t o1 = (size_t)(i0 + br1) * EMB + col;
        *(uint32_t*)(g_xhi + o0) = h0;
        *(uint32_t*)(g_xlo + o0) = pack_bf16x2(e0, e1);
        *(uint32_t*)(g_xhi + o1) = h1;
        *(uint32_t*)(g_xlo + o1) = pack_bf16x2(e2, e3);
    }
}

// ---------------------------------------------------------------------------
extern "C" void kernel_launch(void* const* d_in, const int* in_sizes, int n_in,
                              void* d_out, int out_size)
{
    const float* x   = (const float*)d_in[0];
    const int*   sim = (const int*)d_in[1];
    const float* Wq  = (const float*)d_in[2];
    const float* bq  = (const float*)d_in[3];
    const float* Wk  = (const float*)d_in[4];
    const float* bk  = (const float*)d_in[5];
    const float* Wv  = (const float*)d_in[6];
    const float* bv  = (const float*)d_in[7];
    const float* Wo  = (const float*)d_in[8];
    const float* bo  = (const float*)d_in[9];
    float* out = (float*)d_out;

    const int n4x = NTOK * EMB / 4;
    const int n4w = EMB * EMB / 4;

    convert_x<<<n4x / 256, 256>>>(x, n4x);
    convert_w<<<dim3(n4w / 256, 4), 256>>>(Wq, Wk, Wv, Wo, n4w);

    gemm_tc<<<dim3(EMB / 64, NTOK / 64, 3), 128>>>(bq, bk, bv, nullptr, 0);

    attn_tc<<<dim3(NTOK / 64, NH), 128>>>(sim);

    gemm_tc<<<dim3(EMB / 64, NTOK / 64, 1), 128>>>(bo, nullptr, nullptr, out, 3);
}

// round 12
// speedup vs baseline: 1.1691x; 1.0292x over previous
#include <cuda_runtime.h>
#include <cuda_bf16.h>
#include <cstdint>

#define NTOK 4096
#define EMB  768
#define NH   12
#define HD   64
#define PADB 72
#define L2E  1.4426950408889634f

// ---------------------------------------------------------------------------
// Scratch (allocation-free device globals)
// ---------------------------------------------------------------------------
__device__ __align__(16) __nv_bfloat16 g_xhi[NTOK * EMB];
__device__ __align__(16) __nv_bfloat16 g_xlo[NTOK * EMB];
__device__ __align__(16) __nv_bfloat16 g_whi[4 * EMB * EMB];
__device__ __align__(16) __nv_bfloat16 g_wlo[4 * EMB * EMB];
__device__ __align__(16) __nv_bfloat16 g_qhi[NH * NTOK * HD];
__device__ __align__(16) __nv_bfloat16 g_qlo[NH * NTOK * HD];
__device__ __align__(16) __nv_bfloat16 g_khi[NH * NTOK * HD];
__device__ __align__(16) __nv_bfloat16 g_klo[NH * NTOK * HD];
__device__ __align__(16) __nv_bfloat16 g_vthi[NH * HD * NTOK];
__device__ __align__(16) __nv_bfloat16 g_vtlo[NH * HD * NTOK];

// ---------------------------------------------------------------------------
// Helpers
// ---------------------------------------------------------------------------
__device__ __forceinline__ uint32_t pack_bf16x2(float lo, float hi) {
    uint32_t r;
    asm("cvt.rn.bf16x2.f32 %0, %1, %2;" : "=r"(r) : "f"(hi), "f"(lo));
    return r;
}

// fast exp2 on the FMA pipe, input <= 0 ; exp2p(0) == 1.0 exactly
__device__ __forceinline__ float exp2p(float t) {
    t = fmaxf(t, -120.f);
    float z  = t + 12582912.f;            // 1.5 * 2^23
    float fi = z - 12582912.f;
    float f  = t - fi;
    float p = fmaf(0.00133335581f, f, 0.00961812911f);
    p = fmaf(p, f, 0.0555041087f);
    p = fmaf(p, f, 0.240226507f);
    p = fmaf(p, f, 0.69314718056f);
    p = fmaf(p, f, 1.0f);
    return p * __int_as_float((__float_as_int(z) + 127) << 23);
}

#define MMA_BF16(d, a, b0, b1)                                             \
    asm volatile(                                                          \
        "mma.sync.aligned.m16n8k16.row.col.f32.bf16.bf16.f32 "            \
        "{%0,%1,%2,%3}, {%4,%5,%6,%7}, {%8,%9}, {%0,%1,%2,%3};"           \
        : "+f"((d)[0]), "+f"((d)[1]), "+f"((d)[2]), "+f"((d)[3])           \
        : "r"((a)[0]), "r"((a)[1]), "r"((a)[2]), "r"((a)[3]),              \
          "r"(b0), "r"(b1))

#define LDM_X4(r, a)                                                       \
    asm volatile("ldmatrix.sync.aligned.m8n8.x4.shared.b16 "               \
                 "{%0,%1,%2,%3}, [%4];"                                    \
                 : "=r"((r)[0]), "=r"((r)[1]), "=r"((r)[2]), "=r"((r)[3])  \
                 : "r"(a))

#define CP16(d, s)                                                         \
    asm volatile("cp.async.cg.shared.global [%0], [%1], 16;"               \
                 :: "r"(d), "l"(s))
#define CP_COMMIT() asm volatile("cp.async.commit_group;" ::: "memory")
#define CP_WAIT0()  asm volatile("cp.async.wait_group 0;" ::: "memory")

__device__ __forceinline__ uint32_t sptr(const void* p) {
    return (uint32_t)__cvta_generic_to_shared(p);
}

// ---------------------------------------------------------------------------
// fp32 -> (bf16 hi, bf16 lo) splits
// ---------------------------------------------------------------------------
__device__ __forceinline__ void split_store(__nv_bfloat16* hi, __nv_bfloat16* lo,
                                            int i, float4 v)
{
    uint32_t h0 = pack_bf16x2(v.x, v.y);
    uint32_t h1 = pack_bf16x2(v.z, v.w);
    float r0 = v.x - __uint_as_float(h0 << 16);
    float r1 = v.y - __uint_as_float(h0 & 0xffff0000u);
    float r2 = v.z - __uint_as_float(h1 << 16);
    float r3 = v.w - __uint_as_float(h1 & 0xffff0000u);
    ((uint32_t*)hi)[2 * i + 0] = h0;
    ((uint32_t*)hi)[2 * i + 1] = h1;
    ((uint32_t*)lo)[2 * i + 0] = pack_bf16x2(r0, r1);
    ((uint32_t*)lo)[2 * i + 1] = pack_bf16x2(r2, r3);
}

__global__ __launch_bounds__(256) void convert_x(const float* __restrict__ src, int n4)
{
    int i = blockIdx.x * blockDim.x + threadIdx.x;
    if (i >= n4) return;
    split_store(g_xhi, g_xlo, i, ((const float4*)src)[i]);
}

__global__ __launch_bounds__(256) void convert_w(const float* __restrict__ w0,
                                                 const float* __restrict__ w1,
                                                 const float* __restrict__ w2,
                                                 const float* __restrict__ w3,
                                                 int n4)
{
    int i = blockIdx.x * blockDim.x + threadIdx.x;
    if (i >= n4) return;
    int wi = blockIdx.y;
    const float* src = (wi == 0) ? w0 : (wi == 1) ? w1 : (wi == 2) ? w2 : w3;
    split_store(g_whi + (size_t)wi * EMB * EMB,
                g_wlo + (size_t)wi * EMB * EMB, i, ((const float4*)src)[i]);
}

// ---------------------------------------------------------------------------
// mma.sync bf16-split GEMM: C = A(4096x768) @ W^T + bias.
// mode = base_mode + blockIdx.z. mode 0/1 -> q/k bf16 hi/lo [h][tok][64];
// mode 2 -> v bf16 hi/lo TRANSPOSED [h][d][tok]; mode 3 -> fp32 outp [N][768].
// Block 64(M) x 64(N), 4 warps. ldmatrix fragments, cp.async loads.
// ---------------------------------------------------------------------------
__global__ __launch_bounds__(128) void gemm_tc(const float* __restrict__ b0,
                                               const float* __restrict__ b1,
                                               const float* __restrict__ b2,
                                               float* __restrict__ outp,
                                               int base_mode)
{
    __shared__ __nv_bfloat16 Ah[64][PADB], Al[64][PADB];
    __shared__ __nv_bfloat16 Bh[64][PADB], Bl[64][PADB];

    int mode = base_mode + blockIdx.z;
    const float* bias = (blockIdx.z == 0) ? b0 : (blockIdx.z == 1) ? b1 : b2;
    const __nv_bfloat16* wh = g_whi + (size_t)mode * EMB * EMB;
    const __nv_bfloat16* wl = g_wlo + (size_t)mode * EMB * EMB;

    int nb = blockIdx.x * 64, mb = blockIdx.y * 64;
    int tid = threadIdx.x, w = tid >> 5, lane = tid & 31;
    int qr = lane >> 2, qc = (lane & 3) * 2;

    uint32_t sAh = sptr(&Ah[0][0]), sAl = sptr(&Al[0][0]);
    uint32_t sBh = sptr(&Bh[0][0]), sBl = sptr(&Bl[0][0]);

    // ldmatrix lane addressing
    int a_r = w * 16 + (lane & 7) + ((lane >> 3) & 1) * 8;
    int a_cb = ((lane >> 4) & 1) * 16;                   // byte offset of k-half
    int b_rl = (lane & 7) + ((lane >> 4) & 1) * 8;       // row within 16-n block
    int b_cb = ((lane >> 3) & 1) * 16;

    float acc[8][4];
    #pragma unroll
    for (int n = 0; n < 8; n++)
        #pragma unroll
        for (int j = 0; j < 4; j++) acc[n][j] = 0.f;

    for (int kc = 0; kc < EMB / 64; kc++) {
        __syncthreads();
        #pragma unroll
        for (int i = 0; i < 4; i++) {
            int idx = tid + i * 128;
            int r = idx >> 3, cb = (idx & 7) * 16;
            const char* ga = (const char*)(g_xhi + (size_t)(mb + r) * EMB + kc * 64) + cb;
            const char* gal = (const char*)(g_xlo + (size_t)(mb + r) * EMB + kc * 64) + cb;
            const char* gb = (const char*)(wh + (size_t)(nb + r) * EMB + kc * 64) + cb;
            const char* gbl = (const char*)(wl + (size_t)(nb + r) * EMB + kc * 64) + cb;
            uint32_t so = (uint32_t)(r * (PADB * 2) + cb);
            CP16(sAh + so, ga);
            CP16(sAl + so, gal);
            CP16(sBh + so, gb);
            CP16(sBl + so, gbl);
        }
        CP_COMMIT();
        CP_WAIT0();
        __syncthreads();

        #pragma unroll
        for (int t = 0; t < 4; t++) {
            uint32_t ah[4], al[4];
            uint32_t aoff = (uint32_t)(a_r * (PADB * 2) + t * 32 + a_cb);
            LDM_X4(ah, sAh + aoff);
            LDM_X4(al, sAl + aoff);
            #pragma unroll
            for (int nbk = 0; nbk < 4; nbk++) {
                uint32_t kh[4], kl[4];
                uint32_t boff = (uint32_t)((nbk * 16 + b_rl) * (PADB * 2) + t * 32 + b_cb);
                LDM_X4(kh, sBh + boff);
                LDM_X4(kl, sBl + boff);
                MMA_BF16(acc[2 * nbk], ah, kh[0], kh[1]);
                MMA_BF16(acc[2 * nbk], ah, kl[0], kl[1]);
                MMA_BF16(acc[2 * nbk], al, kh[0], kh[1]);
                MMA_BF16(acc[2 * nbk + 1], ah, kh[2], kh[3]);
                MMA_BF16(acc[2 * nbk + 1], ah, kl[2], kl[3]);
                MMA_BF16(acc[2 * nbk + 1], al, kh[2], kh[3]);
            }
        }
    }

    int r0 = mb + w * 16 + qr;
    if (mode == 3) {
        #pragma unroll
        for (int n = 0; n < 8; n++) {
            int col = nb + n * 8 + qc;
            float2 v0 = {acc[n][0] + bias[col], acc[n][1] + bias[col + 1]};
            float2 v1 = {acc[n][2] + bias[col], acc[n][3] + bias[col + 1]};
            *(float2*)(outp + (size_t)r0 * EMB + col) = v0;
            *(float2*)(outp + (size_t)(r0 + 8) * EMB + col) = v1;
        }
    } else if (mode == 2) {
        // V: write bf16 hi/lo directly TRANSPOSED into g_vt [h][d][tok]
        int hh = blockIdx.x;
        #pragma unroll
        for (int n = 0; n < 8; n++) {
            int d = n * 8 + qc;
            float bb0 = bias[nb + d], bb1 = bias[nb + d + 1];
            #pragma unroll
            for (int half = 0; half < 2; half++) {
                float v0 = acc[n][half * 2 + 0] + bb0;
                float v1 = acc[n][half * 2 + 1] + bb1;
                int tok = r0 + half * 8;
                uint32_t ph = pack_bf16x2(v0, v1);
                float e0 = v0 - __uint_as_float(ph << 16);
                float e1 = v1 - __uint_as_float(ph & 0xffff0000u);
                uint32_t pe = pack_bf16x2(e0, e1);
                size_t o0 = ((size_t)hh * HD + d) * NTOK + tok;
                size_t o1 = ((size_t)hh * HD + d + 1) * NTOK + tok;
                g_vthi[o0] = __ushort_as_bfloat16((unsigned short)(ph & 0xffffu));
                g_vthi[o1] = __ushort_as_bfloat16((unsigned short)(ph >> 16));
                g_vtlo[o0] = __ushort_as_bfloat16((unsigned short)(pe & 0xffffu));
                g_vtlo[o1] = __ushort_as_bfloat16((unsigned short)(pe >> 16));
            }
        }
    } else {
        __nv_bfloat16* dh = (mode == 0) ? g_qhi : g_khi;
        __nv_bfloat16* dl = (mode == 0) ? g_qlo : g_klo;
        int hh = blockIdx.x;
        #pragma unroll
        for (int n = 0; n < 8; n++) {
            int d = n * 8 + qc;
            float bb0 = bias[nb + d], bb1 = bias[nb + d + 1];
            #pragma unroll
            for (int half = 0; half < 2; half++) {
                float v0 = acc[n][half * 2 + 0] + bb0;
                float v1 = acc[n][half * 2 + 1] + bb1;
                uint32_t ph = pack_bf16x2(v0, v1);
                float e0 = v0 - __uint_as_float(ph << 16);
                float e1 = v1 - __uint_as_float(ph & 0xffff0000u);
                size_t off = ((size_t)hh * NTOK + r0 + half * 8) * HD + d;
                *(uint32_t*)(dh + off) = ph;
                *(uint32_t*)(dl + off) = pack_bf16x2(e0, e1);
            }
        }
    }
}

// ---------------------------------------------------------------------------
// Tensor-core flash attention. Block = 64 queries x 1 head, 4 warps.
// __launch_bounds__(128, 4): cap regs at 128 -> 4 blocks/SM (16 warps).
// Skip-rescale fast path when the running max is unchanged (alpha == 1).
// ---------------------------------------------------------------------------
__global__ void __launch_bounds__(128, 4) attn_tc(const int* __restrict__ sim)
{
    __shared__ __nv_bfloat16 Kh[64][PADB], Kl[64][PADB];
    __shared__ __nv_bfloat16 Vh[64][PADB], Vl[64][PADB];   // [d][tok]
    __shared__ __align__(16) unsigned char bc[64][64];
    __shared__ int sims[640];

    int h = blockIdx.y, i0 = blockIdx.x * 64;
    int tid = threadIdx.x, w = tid >> 5, lane = tid & 31;
    int qr = lane >> 2, qc = (lane & 3) * 2;

    for (int t = tid; t < 640; t += 128) sims[t] = sim[(size_t)i0 * 10 + t];

    // Persistent Q fragments from global
    uint32_t qh[4][4], ql[4][4];
    {
        const __nv_bfloat16* qbh = g_qhi + ((size_t)h * NTOK + i0 + w * 16) * HD;
        const __nv_bfloat16* qbl = g_qlo + ((size_t)h * NTOK + i0 + w * 16) * HD;
        #pragma unroll
        for (int t = 0; t < 4; t++)
            #pragma unroll
            for (int j = 0; j < 4; j++) {
                int r = qr + (j & 1) * 8;
                int c = t * 16 + qc + (j >> 1) * 8;
                qh[t][j] = *(const uint32_t*)(qbh + (size_t)r * HD + c);
                ql[t][j] = *(const uint32_t*)(qbl + (size_t)r * HD + c);
            }
    }

    const __nv_bfloat16* kbh = g_khi + (size_t)h * NTOK * HD;
    const __nv_bfloat16* kbl = g_klo + (size_t)h * NTOK * HD;
    const __nv_bfloat16* vbh = g_vthi + (size_t)h * HD * NTOK;
    const __nv_bfloat16* vbl = g_vtlo + (size_t)h * HD * NTOK;

    uint32_t sKh = sptr(&Kh[0][0]), sKl = sptr(&Kl[0][0]);
    uint32_t sVh = sptr(&Vh[0][0]), sVl = sptr(&Vl[0][0]);

    int b_rl = (lane & 7) + ((lane >> 4) & 1) * 8;
    int b_cb = ((lane >> 3) & 1) * 16;

    float o[8][4];
    #pragma unroll
    for (int n = 0; n < 8; n++)
        #pragma unroll
        for (int j = 0; j < 4; j++) o[n][j] = 0.f;
    float m0 = -1e30f, m1 = -1e30f, l0 = 0.f, l1 = 0.f;
    int br0 = w * 16 + qr, br1 = br0 + 8;

    for (int kt = 0; kt < NTOK / 64; kt++) {
        int j0 = kt * 64;
        __syncthreads();
        #pragma unroll
        for (int i = 0; i < 4; i++) {
            int idx = tid + i * 128;
            int r = idx >> 3, cb = (idx & 7) * 16;
            uint32_t so = (uint32_t)(r * (PADB * 2) + cb);
            CP16(sKh + so, (const char*)(kbh + (size_t)(j0 + r) * HD) + cb);
            CP16(sKl + so, (const char*)(kbl + (size_t)(j0 + r) * HD) + cb);
            CP16(sVh + so, (const char*)(vbh + (size_t)r * NTOK + j0) + cb);
            CP16(sVl + so, (const char*)(vbl + (size_t)r * NTOK + j0) + cb);
        }
        CP_COMMIT();
        for (int idx = tid; idx < 256; idx += 128)
            *(uint4*)(&bc[0][0] + idx * 16) = make_uint4(0u, 0u, 0u, 0u);
        CP_WAIT0();
        __syncthreads();
        if (tid < 64) {
            #pragma unroll
            for (int s5 = 0; s5 < 10; s5++) {
                int rel = sims[tid * 10 + s5] - j0;
                if ((unsigned)rel < 64u) bc[tid][rel]++;
            }
        }
        __syncthreads();

        // ---- S = Q K^T (3-pass bf16 split) ----
        float s[8][4];
        #pragma unroll
        for (int n = 0; n < 8; n++)
            #pragma unroll
            for (int j = 0; j < 4; j++) s[n][j] = 0.f;
        #pragma unroll
        for (int t = 0; t < 4; t++) {
            #pragma unroll
            for (int nbk = 0; nbk < 4; nbk++) {
                uint32_t kh[4], kl[4];
                uint32_t boff = (uint32_t)((nbk * 16 + b_rl) * (PADB * 2) + t * 32 + b_cb);
                LDM_X4(kh, sKh + boff);
                LDM_X4(kl, sKl + boff);
                MMA_BF16(s[2 * nbk], qh[t], kh[0], kh[1]);
                MMA_BF16(s[2 * nbk], qh[t], kl[0], kl[1]);
                MMA_BF16(s[2 * nbk], ql[t], kh[0], kh[1]);
                MMA_BF16(s[2 * nbk + 1], qh[t], kh[2], kh[3]);
                MMA_BF16(s[2 * nbk + 1], qh[t], kl[2], kl[3]);
                MMA_BF16(s[2 * nbk + 1], ql[t], kh[2], kh[3]);
            }
        }

        // ---- scale + bias + online softmax ----
        float mx0 = -1e30f, mx1 = -1e30f;
        #pragma unroll
        for (int n = 0; n < 8; n++) {
            int c0i = n * 8 + qc;
            s[n][0] = fmaf(s[n][0], 0.125f, (float)bc[br0][c0i]);
            s[n][1] = fmaf(s[n][1], 0.125f, (float)bc[br0][c0i + 1]);
            s[n][2] = fmaf(s[n][2], 0.125f, (float)bc[br1][c0i]);
            s[n][3] = fmaf(s[n][3], 0.125f, (float)bc[br1][c0i + 1]);
            mx0 = fmaxf(mx0, fmaxf(s[n][0], s[n][1]));
            mx1 = fmaxf(mx1, fmaxf(s[n][2], s[n][3]));
        }
        #pragma unroll
        for (int off = 1; off <= 2; off <<= 1) {
            mx0 = fmaxf(mx0, __shfl_xor_sync(0xffffffffu, mx0, off));
            mx1 = fmaxf(mx1, __shfl_xor_sync(0xffffffffu, mx1, off));
        }
        float mn0 = fmaxf(m0, mx0), mn1 = fmaxf(m1, mx1);

        float rs0 = 0.f, rs1 = 0.f;
        uint32_t pa[4][4], pl[4][4];
        #pragma unroll
        for (int n = 0; n < 8; n++) {
            float p0 = exp2p((s[n][0] - mn0) * L2E);
            float p1 = exp2p((s[n][1] - mn0) * L2E);
            float p2 = exp2p((s[n][2] - mn1) * L2E);
            float p3 = exp2p((s[n][3] - mn1) * L2E);
            rs0 += p0 + p1;
            rs1 += p2 + p3;
            uint32_t hp01 = pack_bf16x2(p0, p1);
            uint32_t hp23 = pack_bf16x2(p2, p3);
            float e0 = p0 - __uint_as_float(hp01 << 16);
            float e1 = p1 - __uint_as_float(hp01 & 0xffff0000u);
            float e2 = p2 - __uint_as_float(hp23 << 16);
            float e3 = p3 - __uint_as_float(hp23 & 0xffff0000u);
            int t = n >> 1, half = (n & 1) * 2;
            pa[t][half + 0] = hp01;
            pa[t][half + 1] = hp23;
            pl[t][half + 0] = pack_bf16x2(e0, e1);
            pl[t][half + 1] = pack_bf16x2(e2, e3);
        }
        #pragma unroll
        for (int off = 1; off <= 2; off <<= 1) {
            rs0 += __shfl_xor_sync(0xffffffffu, rs0, off);
            rs1 += __shfl_xor_sync(0xffffffffu, rs1, off);
        }

        // Skip-rescale fast path: if no lane's max moved, alpha == 1 exactly.
        if (__all_sync(0xffffffffu, (mn0 == m0) & (mn1 == m1))) {
            l0 += rs0;
            l1 += rs1;
        } else {
            float a0 = exp2p((m0 - mn0) * L2E), a1 = exp2p((m1 - mn1) * L2E);
            l0 = l0 * a0 + rs0;
            l1 = l1 * a1 + rs1;
            m0 = mn0;
            m1 = mn1;
            #pragma unroll
            for (int n = 0; n < 8; n++) {
                o[n][0] *= a0; o[n][1] *= a0;
                o[n][2] *= a1; o[n][3] *= a1;
            }
        }

        // ---- O += P V (3-pass bf16 split) ----
        #pragma unroll
        for (int t = 0; t < 4; t++) {
            #pragma unroll
            for (int nbk = 0; nbk < 4; nbk++) {
                uint32_t vh[4], vl[4];
                uint32_t boff = (uint32_t)((nbk * 16 + b_rl) * (PADB * 2) + t * 32 + b_cb);
                LDM_X4(vh, sVh + boff);
                LDM_X4(vl, sVl + boff);
                MMA_BF16(o[2 * nbk], pa[t], vh[0], vh[1]);
                MMA_BF16(o[2 * nbk], pa[t], vl[0], vl[1]);
                MMA_BF16(o[2 * nbk], pl[t], vh[0], vh[1]);
                MMA_BF16(o[2 * nbk + 1], pa[t], vh[2], vh[3]);
                MMA_BF16(o[2 * nbk + 1], pa[t], vl[2], vl[3]);
                MMA_BF16(o[2 * nbk + 1], pl[t], vh[2], vh[3]);
            }
        }
    }

    // Fused epilogue: split-store O directly as O-projection input
    float il0 = 1.f / l0, il1 = 1.f / l1;
    #pragma unroll
    for (int n = 0; n < 8; n++) {
        int col = h * HD + n * 8 + qc;
        float v0 = o[n][0] * il0, v1 = o[n][1] * il0;
        float v2 = o[n][2] * il1, v3 = o[n][3] * il1;
        uint32_t h0 = pack_bf16x2(v0, v1);
        uint32_t h1 = pack_bf16x2(v2, v3);
        float e0 = v0 - __uint_as_float(h0 << 16);
        float e1 = v1 - __uint_as_float(h0 & 0xffff0000u);
        float e2 = v2 - __uint_as_float(h1 << 16);
        float e3 = v3 - __uint_as_float(h1 & 0xffff0000u);
        size_t o0 = (size_t)(i0 + br0) * EMB + col;
        size_t o1 = (size_t)(i0 + br1) * EMB + col;
        *(uint32_t*)(g_xhi + o0) = h0;
        *(uint32_t*)(g_xlo + o0) = pack_bf16x2(e0, e1);
        *(uint32_t*)(g_xhi + o1) = h1;
        *(uint32_t*)(g_xlo + o1) = pack_bf16x2(e2, e3);
    }
}

// ---------------------------------------------------------------------------
extern "C" void kernel_launch(void* const* d_in, const int* in_sizes, int n_in,
                              void* d_out, int out_size)
{
    const float* x   = (const float*)d_in[0];
    const int*   sim = (const int*)d_in[1];
    const float* Wq  = (const float*)d_in[2];
    const float* bq  = (const float*)d_in[3];
    const float* Wk  = (const float*)d_in[4];
    const float* bk  = (const float*)d_in[5];
    const float* Wv  = (const float*)d_in[6];
    const float* bv  = (const float*)d_in[7];
    const float* Wo  = (const float*)d_in[8];
    const float* bo  = (const float*)d_in[9];
    float* out = (float*)d_out;

    const int n4x = NTOK * EMB / 4;
    const int n4w = EMB * EMB / 4;

    convert_x<<<n4x / 256, 256>>>(x, n4x);
    convert_w<<<dim3(n4w / 256, 4), 256>>>(Wq, Wk, Wv, Wo, n4w);

    gemm_tc<<<dim3(EMB / 64, NTOK / 64, 3), 128>>>(bq, bk, bv, nullptr, 0);

    attn_tc<<<dim3(NTOK / 64, NH), 128>>>(sim);

    gemm_tc<<<dim3(EMB / 64, NTOK / 64, 1), 128>>>(bo, nullptr, nullptr, out, 3);
}

// round 13
// speedup vs baseline: 1.2212x; 1.0446x over previous
#include <cuda_runtime.h>
#include <cuda_bf16.h>
#include <cstdint>

#define NTOK 4096
#define EMB  768
#define NH   12
#define HD   64
#define PADB 72
#define L2E  1.4426950408889634f

// ---------------------------------------------------------------------------
// Scratch (allocation-free device globals)
// ---------------------------------------------------------------------------
__device__ __align__(16) __nv_bfloat16 g_xhi[NTOK * EMB];
__device__ __align__(16) __nv_bfloat16 g_xlo[NTOK * EMB];
__device__ __align__(16) __nv_bfloat16 g_whi[4 * EMB * EMB];
__device__ __align__(16) __nv_bfloat16 g_wlo[4 * EMB * EMB];
__device__ __align__(16) __nv_bfloat16 g_qhi[NH * NTOK * HD];
__device__ __align__(16) __nv_bfloat16 g_qlo[NH * NTOK * HD];
__device__ __align__(16) __nv_bfloat16 g_khi[NH * NTOK * HD];
__device__ __align__(16) __nv_bfloat16 g_klo[NH * NTOK * HD];
__device__ __align__(16) __nv_bfloat16 g_vthi[NH * HD * NTOK];
__device__ __align__(16) __nv_bfloat16 g_vtlo[NH * HD * NTOK];

// ---------------------------------------------------------------------------
// Helpers
// ---------------------------------------------------------------------------
__device__ __forceinline__ uint32_t pack_bf16x2(float lo, float hi) {
    uint32_t r;
    asm("cvt.rn.bf16x2.f32 %0, %1, %2;" : "=r"(r) : "f"(hi), "f"(lo));
    return r;
}

// fast exp2 on the FMA pipe, input <= 0 ; exp2p(0) == 1.0 exactly
__device__ __forceinline__ float exp2p(float t) {
    t = fmaxf(t, -120.f);
    float z  = t + 12582912.f;            // 1.5 * 2^23
    float fi = z - 12582912.f;
    float f  = t - fi;
    float p = fmaf(0.00133335581f, f, 0.00961812911f);
    p = fmaf(p, f, 0.0555041087f);
    p = fmaf(p, f, 0.240226507f);
    p = fmaf(p, f, 0.69314718056f);
    p = fmaf(p, f, 1.0f);
    return p * __int_as_float((__float_as_int(z) + 127) << 23);
}

#define MMA_BF16(d, a, b0, b1)                                             \
    asm volatile(                                                          \
        "mma.sync.aligned.m16n8k16.row.col.f32.bf16.bf16.f32 "            \
        "{%0,%1,%2,%3}, {%4,%5,%6,%7}, {%8,%9}, {%0,%1,%2,%3};"           \
        : "+f"((d)[0]), "+f"((d)[1]), "+f"((d)[2]), "+f"((d)[3])           \
        : "r"((a)[0]), "r"((a)[1]), "r"((a)[2]), "r"((a)[3]),              \
          "r"(b0), "r"(b1))

#define LDM_X4(r, a)                                                       \
    asm volatile("ldmatrix.sync.aligned.m8n8.x4.shared.b16 "               \
                 "{%0,%1,%2,%3}, [%4];"                                    \
                 : "=r"((r)[0]), "=r"((r)[1]), "=r"((r)[2]), "=r"((r)[3])  \
                 : "r"(a))

#define CP16(d, s)                                                         \
    asm volatile("cp.async.cg.shared.global [%0], [%1], 16;"               \
                 :: "r"(d), "l"(s))
#define CP_COMMIT() asm volatile("cp.async.commit_group;" ::: "memory")
#define CP_WAIT0()  asm volatile("cp.async.wait_group 0;" ::: "memory")
#define CP_WAIT1()  asm volatile("cp.async.wait_group 1;" ::: "memory")

__device__ __forceinline__ uint32_t sptr(const void* p) {
    return (uint32_t)__cvta_generic_to_shared(p);
}

// ---------------------------------------------------------------------------
// fp32 -> (bf16 hi, bf16 lo) splits
// ---------------------------------------------------------------------------
__device__ __forceinline__ void split_store(__nv_bfloat16* hi, __nv_bfloat16* lo,
                                            int i, float4 v)
{
    uint32_t h0 = pack_bf16x2(v.x, v.y);
    uint32_t h1 = pack_bf16x2(v.z, v.w);
    float r0 = v.x - __uint_as_float(h0 << 16);
    float r1 = v.y - __uint_as_float(h0 & 0xffff0000u);
    float r2 = v.z - __uint_as_float(h1 << 16);
    float r3 = v.w - __uint_as_float(h1 & 0xffff0000u);
    ((uint32_t*)hi)[2 * i + 0] = h0;
    ((uint32_t*)hi)[2 * i + 1] = h1;
    ((uint32_t*)lo)[2 * i + 0] = pack_bf16x2(r0, r1);
    ((uint32_t*)lo)[2 * i + 1] = pack_bf16x2(r2, r3);
}

__global__ __launch_bounds__(256) void convert_x(const float* __restrict__ src, int n4)
{
    int i = blockIdx.x * blockDim.x + threadIdx.x;
    if (i >= n4) return;
    split_store(g_xhi, g_xlo, i, ((const float4*)src)[i]);
}

__global__ __launch_bounds__(256) void convert_w(const float* __restrict__ w0,
                                                 const float* __restrict__ w1,
                                                 const float* __restrict__ w2,
                                                 const float* __restrict__ w3,
                                                 int n4)
{
    int i = blockIdx.x * blockDim.x + threadIdx.x;
    if (i >= n4) return;
    int wi = blockIdx.y;
    const float* src = (wi == 0) ? w0 : (wi == 1) ? w1 : (wi == 2) ? w2 : w3;
    split_store(g_whi + (size_t)wi * EMB * EMB,
                g_wlo + (size_t)wi * EMB * EMB, i, ((const float4*)src)[i]);
}

// ---------------------------------------------------------------------------
// mma.sync bf16-split GEMM (unchanged from 771us build).
// ---------------------------------------------------------------------------
__global__ __launch_bounds__(128) void gemm_tc(const float* __restrict__ b0,
                                               const float* __restrict__ b1,
                                               const float* __restrict__ b2,
                                               float* __restrict__ outp,
                                               int base_mode)
{
    __shared__ __nv_bfloat16 Ah[64][PADB], Al[64][PADB];
    __shared__ __nv_bfloat16 Bh[64][PADB], Bl[64][PADB];

    int mode = base_mode + blockIdx.z;
    const float* bias = (blockIdx.z == 0) ? b0 : (blockIdx.z == 1) ? b1 : b2;
    const __nv_bfloat16* wh = g_whi + (size_t)mode * EMB * EMB;
    const __nv_bfloat16* wl = g_wlo + (size_t)mode * EMB * EMB;

    int nb = blockIdx.x * 64, mb = blockIdx.y * 64;
    int tid = threadIdx.x, w = tid >> 5, lane = tid & 31;
    int qr = lane >> 2, qc = (lane & 3) * 2;

    uint32_t sAh = sptr(&Ah[0][0]), sAl = sptr(&Al[0][0]);
    uint32_t sBh = sptr(&Bh[0][0]), sBl = sptr(&Bl[0][0]);

    int a_r = w * 16 + (lane & 7) + ((lane >> 3) & 1) * 8;
    int a_cb = ((lane >> 4) & 1) * 16;
    int b_rl = (lane & 7) + ((lane >> 4) & 1) * 8;
    int b_cb = ((lane >> 3) & 1) * 16;

    float acc[8][4];
    #pragma unroll
    for (int n = 0; n < 8; n++)
        #pragma unroll
        for (int j = 0; j < 4; j++) acc[n][j] = 0.f;

    for (int kc = 0; kc < EMB / 64; kc++) {
        __syncthreads();
        #pragma unroll
        for (int i = 0; i < 4; i++) {
            int idx = tid + i * 128;
            int r = idx >> 3, cb = (idx & 7) * 16;
            const char* ga = (const char*)(g_xhi + (size_t)(mb + r) * EMB + kc * 64) + cb;
            const char* gal = (const char*)(g_xlo + (size_t)(mb + r) * EMB + kc * 64) + cb;
            const char* gb = (const char*)(wh + (size_t)(nb + r) * EMB + kc * 64) + cb;
            const char* gbl = (const char*)(wl + (size_t)(nb + r) * EMB + kc * 64) + cb;
            uint32_t so = (uint32_t)(r * (PADB * 2) + cb);
            CP16(sAh + so, ga);
            CP16(sAl + so, gal);
            CP16(sBh + so, gb);
            CP16(sBl + so, gbl);
        }
        CP_COMMIT();
        CP_WAIT0();
        __syncthreads();

        #pragma unroll
        for (int t = 0; t < 4; t++) {
            uint32_t ah[4], al[4];
            uint32_t aoff = (uint32_t)(a_r * (PADB * 2) + t * 32 + a_cb);
            LDM_X4(ah, sAh + aoff);
            LDM_X4(al, sAl + aoff);
            #pragma unroll
            for (int nbk = 0; nbk < 4; nbk++) {
                uint32_t kh[4], kl[4];
                uint32_t boff = (uint32_t)((nbk * 16 + b_rl) * (PADB * 2) + t * 32 + b_cb);
                LDM_X4(kh, sBh + boff);
                LDM_X4(kl, sBl + boff);
                MMA_BF16(acc[2 * nbk], ah, kh[0], kh[1]);
                MMA_BF16(acc[2 * nbk], ah, kl[0], kl[1]);
                MMA_BF16(acc[2 * nbk], al, kh[0], kh[1]);
                MMA_BF16(acc[2 * nbk + 1], ah, kh[2], kh[3]);
                MMA_BF16(acc[2 * nbk + 1], ah, kl[2], kl[3]);
                MMA_BF16(acc[2 * nbk + 1], al, kh[2], kh[3]);
            }
        }
    }

    int r0 = mb + w * 16 + qr;
    if (mode == 3) {
        #pragma unroll
        for (int n = 0; n < 8; n++) {
            int col = nb + n * 8 + qc;
            float2 v0 = {acc[n][0] + bias[col], acc[n][1] + bias[col + 1]};
            float2 v1 = {acc[n][2] + bias[col], acc[n][3] + bias[col + 1]};
            *(float2*)(outp + (size_t)r0 * EMB + col) = v0;
            *(float2*)(outp + (size_t)(r0 + 8) * EMB + col) = v1;
        }
    } else if (mode == 2) {
        int hh = blockIdx.x;
        #pragma unroll
        for (int n = 0; n < 8; n++) {
            int d = n * 8 + qc;
            float bb0 = bias[nb + d], bb1 = bias[nb + d + 1];
            #pragma unroll
            for (int half = 0; half < 2; half++) {
                float v0 = acc[n][half * 2 + 0] + bb0;
                float v1 = acc[n][half * 2 + 1] + bb1;
                int tok = r0 + half * 8;
                uint32_t ph = pack_bf16x2(v0, v1);
                float e0 = v0 - __uint_as_float(ph << 16);
                float e1 = v1 - __uint_as_float(ph & 0xffff0000u);
                uint32_t pe = pack_bf16x2(e0, e1);
                size_t o0 = ((size_t)hh * HD + d) * NTOK + tok;
                size_t o1 = ((size_t)hh * HD + d + 1) * NTOK + tok;
                g_vthi[o0] = __ushort_as_bfloat16((unsigned short)(ph & 0xffffu));
                g_vthi[o1] = __ushort_as_bfloat16((unsigned short)(ph >> 16));
                g_vtlo[o0] = __ushort_as_bfloat16((unsigned short)(pe & 0xffffu));
                g_vtlo[o1] = __ushort_as_bfloat16((unsigned short)(pe >> 16));
            }
        }
    } else {
        __nv_bfloat16* dh = (mode == 0) ? g_qhi : g_khi;
        __nv_bfloat16* dl = (mode == 0) ? g_qlo : g_klo;
        int hh = blockIdx.x;
        #pragma unroll
        for (int n = 0; n < 8; n++) {
            int d = n * 8 + qc;
            float bb0 = bias[nb + d], bb1 = bias[nb + d + 1];
            #pragma unroll
            for (int half = 0; half < 2; half++) {
                float v0 = acc[n][half * 2 + 0] + bb0;
                float v1 = acc[n][half * 2 + 1] + bb1;
                uint32_t ph = pack_bf16x2(v0, v1);
                float e0 = v0 - __uint_as_float(ph << 16);
                float e1 = v1 - __uint_as_float(ph & 0xffff0000u);
                size_t off = ((size_t)hh * NTOK + r0 + half * 8) * HD + d;
                *(uint32_t*)(dh + off) = ph;
                *(uint32_t*)(dl + off) = pack_bf16x2(e0, e1);
            }
        }
    }
}

// ---------------------------------------------------------------------------
// Tensor-core flash attention, software-pipelined.
// Block = 64 queries x 1 head, 4 warps. K double-buffered, V single-buffered:
//   wait K_t -> issue V_t -> QK (V_t loads underneath) -> issue K_{t+1}
//   -> softmax -> wait V_t -> PV.  2 barriers/tile; bias counts double-buffered
//   (zero after B1, scatter after B2). Numerics identical to the 771us build.
// Dynamic smem layout (66048 B -> 3 blocks/SM):
//   0      K0 hi (9216) | 9216  K0 lo | 18432 K1 hi | 27648 K1 lo
//   36864  V hi (9216)  | 46080 V lo
//   55296  bc[2][64][64] (8192) | 63488 sims (2560)
// ---------------------------------------------------------------------------
#define AT_K(b)  ((uint32_t)(b) * 18432u)
#define AT_VH    36864u
#define AT_VL    46080u
#define AT_BC    55296
#define AT_SIM   63488
#define AT_SMEM  66048

__global__ void __launch_bounds__(128, 3) attn_tc(const int* __restrict__ sim)
{
    extern __shared__ char smx[];
    uint32_t sb = sptr(smx);
    unsigned char (*bc)[64][64] = (unsigned char (*)[64][64])(smx + AT_BC);
    int* sims = (int*)(smx + AT_SIM);

    int h = blockIdx.y, i0 = blockIdx.x * 64;
    int tid = threadIdx.x, w = tid >> 5, lane = tid & 31;
    int qr = lane >> 2, qc = (lane & 3) * 2;

    for (int t = tid; t < 640; t += 128) sims[t] = sim[(size_t)i0 * 10 + t];

    // Persistent Q fragments from global
    uint32_t qh[4][4], ql[4][4];
    {
        const __nv_bfloat16* qbh = g_qhi + ((size_t)h * NTOK + i0 + w * 16) * HD;
        const __nv_bfloat16* qbl = g_qlo + ((size_t)h * NTOK + i0 + w * 16) * HD;
        #pragma unroll
        for (int t = 0; t < 4; t++)
            #pragma unroll
            for (int j = 0; j < 4; j++) {
                int r = qr + (j & 1) * 8;
                int c = t * 16 + qc + (j >> 1) * 8;
                qh[t][j] = *(const uint32_t*)(qbh + (size_t)r * HD + c);
                ql[t][j] = *(const uint32_t*)(qbl + (size_t)r * HD + c);
            }
    }

    const __nv_bfloat16* kbh = g_khi + (size_t)h * NTOK * HD;
    const __nv_bfloat16* kbl = g_klo + (size_t)h * NTOK * HD;
    const __nv_bfloat16* vbh = g_vthi + (size_t)h * HD * NTOK;
    const __nv_bfloat16* vbl = g_vtlo + (size_t)h * HD * NTOK;

    int b_rl = (lane & 7) + ((lane >> 4) & 1) * 8;
    int b_cb = ((lane >> 3) & 1) * 16;

    auto issueK = [&](int kt) {
        uint32_t off = sb + AT_K(kt & 1);
        int j0 = kt * 64;
        #pragma unroll
        for (int i = 0; i < 4; i++) {
            int idx = tid + i * 128;
            int r = idx >> 3, cb = (idx & 7) * 16;
            uint32_t so = (uint32_t)(r * (PADB * 2) + cb);
            CP16(off + so,        (const char*)(kbh + (size_t)(j0 + r) * HD) + cb);
            CP16(off + 9216 + so, (const char*)(kbl + (size_t)(j0 + r) * HD) + cb);
        }
        CP_COMMIT();
    };
    auto issueV = [&](int kt) {
        int j0 = kt * 64;
        #pragma unroll
        for (int i = 0; i < 4; i++) {
            int idx = tid + i * 128;
            int r = idx >> 3, cb = (idx & 7) * 16;
            uint32_t so = (uint32_t)(r * (PADB * 2) + cb);
            CP16(sb + AT_VH + so, (const char*)(vbh + (size_t)r * NTOK + j0) + cb);
            CP16(sb + AT_VL + so, (const char*)(vbl + (size_t)r * NTOK + j0) + cb);
        }
        CP_COMMIT();
    };

    float o[8][4];
    #pragma unroll
    for (int n = 0; n < 8; n++)
        #pragma unroll
        for (int j = 0; j < 4; j++) o[n][j] = 0.f;
    float m0 = -1e30f, m1 = -1e30f, l0 = 0.f, l1 = 0.f;
    int br0 = w * 16 + qr, br1 = br0 + 8;

    const int NT = NTOK / 64;

    // Prologue: start K_0; zero both bias-count buffers; scatter tile 0.
    issueK(0);
    for (int idx = tid; idx < 512; idx += 128)
        ((uint4*)(smx + AT_BC))[idx] = make_uint4(0u, 0u, 0u, 0u);
    __syncthreads();
    if (tid < 64) {
        #pragma unroll
        for (int s5 = 0; s5 < 10; s5++) {
            int rel = sims[tid * 10 + s5];
            if ((unsigned)rel < 64u) (*bc)[tid][rel]++;  // bc[0]
        }
    }

    for (int kt = 0; kt < NT; kt++) {
        CP_WAIT0();            // K_kt resident (only pending group)
        __syncthreads();       // B1: also orders PV_{kt-1} before V_kt overwrite

        issueV(kt);

        // zero bc[(kt+1)&1] (last read at softmax kt-1; ordered by B1)
        {
            uint4* bz = (uint4*)(smx + AT_BC + ((kt + 1) & 1) * 4096);
            for (int idx = tid; idx < 256; idx += 128)
                bz[idx] = make_uint4(0u, 0u, 0u, 0u);
        }

        // ---- S = Q K^T (3-pass bf16 split) from K[(kt)&1] ----
        uint32_t sKh = sb + AT_K(kt & 1), sKl = sKh + 9216;
        float s[8][4];
        #pragma unroll
        for (int n = 0; n < 8; n++)
            #pragma unroll
            for (int j = 0; j < 4; j++) s[n][j] = 0.f;
        #pragma unroll
        for (int t = 0; t < 4; t++) {
            #pragma unroll
            for (int nbk = 0; nbk < 4; nbk++) {
                uint32_t kh[4], kl[4];
                uint32_t boff = (uint32_t)((nbk * 16 + b_rl) * (PADB * 2) + t * 32 + b_cb);
                LDM_X4(kh, sKh + boff);
                LDM_X4(kl, sKl + boff);
                MMA_BF16(s[2 * nbk], qh[t], kh[0], kh[1]);
                MMA_BF16(s[2 * nbk + 1], qh[t], kh[2], kh[3]);
                MMA_BF16(s[2 * nbk], qh[t], kl[0], kl[1]);
                MMA_BF16(s[2 * nbk + 1], qh[t], kl[2], kl[3]);
                MMA_BF16(s[2 * nbk], ql[t], kh[0], kh[1]);
                MMA_BF16(s[2 * nbk + 1], ql[t], kh[2], kh[3]);
            }
        }

        if (kt + 1 < NT) issueK(kt + 1);   // into K[(kt+1)&1], free since B1

        // ---- scale + bias + online softmax (reads bc[kt&1]) ----
        unsigned char (*bcc)[64] = (unsigned char (*)[64])(smx + AT_BC + (kt & 1) * 4096);
        float mx0 = -1e30f, mx1 = -1e30f;
        #pragma unroll
        for (int n = 0; n < 8; n++) {
            int c0i = n * 8 + qc;
            s[n][0] = fmaf(s[n][0], 0.125f, (float)bcc[br0][c0i]);
            s[n][1] = fmaf(s[n][1], 0.125f, (float)bcc[br0][c0i + 1]);
            s[n][2] = fmaf(s[n][2], 0.125f, (float)bcc[br1][c0i]);
            s[n][3] = fmaf(s[n][3], 0.125f, (float)bcc[br1][c0i + 1]);
            mx0 = fmaxf(mx0, fmaxf(s[n][0], s[n][1]));
            mx1 = fmaxf(mx1, fmaxf(s[n][2], s[n][3]));
        }
        #pragma unroll
        for (int off = 1; off <= 2; off <<= 1) {
            mx0 = fmaxf(mx0, __shfl_xor_sync(0xffffffffu, mx0, off));
            mx1 = fmaxf(mx1, __shfl_xor_sync(0xffffffffu, mx1, off));
        }
        float mn0 = fmaxf(m0, mx0), mn1 = fmaxf(m1, mx1);

        float rs0 = 0.f, rs1 = 0.f;
        uint32_t pa[4][4], pl[4][4];
        #pragma unroll
        for (int n = 0; n < 8; n++) {
            float p0 = exp2p((s[n][0] - mn0) * L2E);
            float p1 = exp2p((s[n][1] - mn0) * L2E);
            float p2 = exp2p((s[n][2] - mn1) * L2E);
            float p3 = exp2p((s[n][3] - mn1) * L2E);
            rs0 += p0 + p1;
            rs1 += p2 + p3;
            uint32_t hp01 = pack_bf16x2(p0, p1);
            uint32_t hp23 = pack_bf16x2(p2, p3);
            float e0 = p0 - __uint_as_float(hp01 << 16);
            float e1 = p1 - __uint_as_float(hp01 & 0xffff0000u);
            float e2 = p2 - __uint_as_float(hp23 << 16);
            float e3 = p3 - __uint_as_float(hp23 & 0xffff0000u);
            int t = n >> 1, half = (n & 1) * 2;
            pa[t][half + 0] = hp01;
            pa[t][half + 1] = hp23;
            pl[t][half + 0] = pack_bf16x2(e0, e1);
            pl[t][half + 1] = pack_bf16x2(e2, e3);
        }
        #pragma unroll
        for (int off = 1; off <= 2; off <<= 1) {
            rs0 += __shfl_xor_sync(0xffffffffu, rs0, off);
            rs1 += __shfl_xor_sync(0xffffffffu, rs1, off);
        }

        if (__all_sync(0xffffffffu, (mn0 == m0) & (mn1 == m1))) {
            l0 += rs0;
            l1 += rs1;
        } else {
            float a0 = exp2p((m0 - mn0) * L2E), a1 = exp2p((m1 - mn1) * L2E);
            l0 = l0 * a0 + rs0;
            l1 = l1 * a1 + rs1;
            m0 = mn0;
            m1 = mn1;
            #pragma unroll
            for (int n = 0; n < 8; n++) {
                o[n][0] *= a0; o[n][1] *= a0;
                o[n][2] *= a1; o[n][3] *= a1;
            }
        }

        // ---- wait V_kt (K_{kt+1} may still be in flight) ----
        if (kt + 1 < NT) { CP_WAIT1(); } else { CP_WAIT0(); }
        __syncthreads();       // B2

        // scatter bias counts for tile kt+1 into bc[(kt+1)&1]
        if (kt + 1 < NT && tid < 64) {
            int jn = (kt + 1) * 64;
            #pragma unroll
            for (int s5 = 0; s5 < 10; s5++) {
                int rel = sims[tid * 10 + s5] - jn;
                if ((unsigned)rel < 64u) bc[(kt + 1) & 1][tid][rel]++;
            }
        }

        // ---- O += P V (3-pass bf16 split) ----
        uint32_t sVh = sb + AT_VH, sVl = sb + AT_VL;
        #pragma unroll
        for (int t = 0; t < 4; t++) {
            #pragma unroll
            for (int nbk = 0; nbk < 4; nbk++) {
                uint32_t vh[4], vl[4];
                uint32_t boff = (uint32_t)((nbk * 16 + b_rl) * (PADB * 2) + t * 32 + b_cb);
                LDM_X4(vh, sVh + boff);
                LDM_X4(vl, sVl + boff);
                MMA_BF16(o[2 * nbk], pa[t], vh[0], vh[1]);
                MMA_BF16(o[2 * nbk + 1], pa[t], vh[2], vh[3]);
                MMA_BF16(o[2 * nbk], pa[t], vl[0], vl[1]);
                MMA_BF16(o[2 * nbk + 1], pa[t], vl[2], vl[3]);
                MMA_BF16(o[2 * nbk], pl[t], vh[0], vh[1]);
                MMA_BF16(o[2 * nbk + 1], pl[t], vh[2], vh[3]);
            }
        }
    }

    // Fused epilogue: split-store O directly as O-projection input
    float il0 = 1.f / l0, il1 = 1.f / l1;
    #pragma unroll
    for (int n = 0; n < 8; n++) {
        int col = h * HD + n * 8 + qc;
        float v0 = o[n][0] * il0, v1 = o[n][1] * il0;
        float v2 = o[n][2] * il1, v3 = o[n][3] * il1;
        uint32_t h0 = pack_bf16x2(v0, v1);
        uint32_t h1 = pack_bf16x2(v2, v3);
        float e0 = v0 - __uint_as_float(h0 << 16);
        float e1 = v1 - __uint_as_float(h0 & 0xffff0000u);
        float e2 = v2 - __uint_as_float(h1 << 16);
        float e3 = v3 - __uint_as_float(h1 & 0xffff0000u);
        size_t o0 = (size_t)(i0 + br0) * EMB + col;
        size_t o1 = (size_t)(i0 + br1) * EMB + col;
        *(uint32_t*)(g_xhi + o0) = h0;
        *(uint32_t*)(g_xlo + o0) = pack_bf16x2(e0, e1);
        *(uint32_t*)(g_xhi + o1) = h1;
        *(uint32_t*)(g_xlo + o1) = pack_bf16x2(e2, e3);
    }
}

// ---------------------------------------------------------------------------
extern "C" void kernel_launch(void* const* d_in, const int* in_sizes, int n_in,
                              void* d_out, int out_size)
{
    const float* x   = (const float*)d_in[0];
    const int*   sim = (const int*)d_in[1];
    const float* Wq  = (const float*)d_in[2];
    const float* bq  = (const float*)d_in[3];
    const float* Wk  = (const float*)d_in[4];
    const float* bk  = (const float*)d_in[5];
    const float* Wv  = (const float*)d_in[6];
    const float* bv  = (const float*)d_in[7];
    const float* Wo  = (const float*)d_in[8];
    const float* bo  = (const float*)d_in[9];
    float* out = (float*)d_out;

    cudaFuncSetAttribute(attn_tc, cudaFuncAttributeMaxDynamicSharedMemorySize, AT_SMEM);

    const int n4x = NTOK * EMB / 4;
    const int n4w = EMB * EMB / 4;

    convert_x<<<n4x / 256, 256>>>(x, n4x);
    convert_w<<<dim3(n4w / 256, 4), 256>>>(Wq, Wk, Wv, Wo, n4w);

    gemm_tc<<<dim3(EMB / 64, NTOK / 64, 3), 128>>>(bq, bk, bv, nullptr, 0);

    attn_tc<<<dim3(NTOK / 64, NH), 128, AT_SMEM>>>(sim);

    gemm_tc<<<dim3(EMB / 64, NTOK / 64, 1), 128>>>(bo, nullptr, nullptr, out, 3);
}

// round 14
// speedup vs baseline: 1.3414x; 1.0984x over previous
#include <cuda_runtime.h>
#include <cuda_bf16.h>
#include <cstdint>

#define NTOK 4096
#define EMB  768
#define NH   12
#define HD   64
#define PADB 72
#define L2E  1.4426950408889634f
#define QSC  (0.125f * 1.4426950408889634f)

// ---------------------------------------------------------------------------
// Scratch (allocation-free device globals)
// ---------------------------------------------------------------------------
__device__ __align__(16) __nv_bfloat16 g_xhi[NTOK * EMB];
__device__ __align__(16) __nv_bfloat16 g_xlo[NTOK * EMB];
__device__ __align__(16) __nv_bfloat16 g_whi[4 * EMB * EMB];
__device__ __align__(16) __nv_bfloat16 g_wlo[4 * EMB * EMB];
__device__ __align__(16) __nv_bfloat16 g_qhi[NH * NTOK * HD];
__device__ __align__(16) __nv_bfloat16 g_qlo[NH * NTOK * HD];
__device__ __align__(16) __nv_bfloat16 g_khi[NH * NTOK * HD];
__device__ __align__(16) __nv_bfloat16 g_klo[NH * NTOK * HD];
__device__ __align__(16) __nv_bfloat16 g_vthi[NH * HD * NTOK];
__device__ __align__(16) __nv_bfloat16 g_vtlo[NH * HD * NTOK];

// ---------------------------------------------------------------------------
// Helpers
// ---------------------------------------------------------------------------
__device__ __forceinline__ uint32_t pack_bf16x2(float lo, float hi) {
    uint32_t r;
    asm("cvt.rn.bf16x2.f32 %0, %1, %2;" : "=r"(r) : "f"(hi), "f"(lo));
    return r;
}

// exp2 for t in [-~60, 0]; NO clamp. exp2nf(0) == 1.0 exactly.
// exponent injected by integer add (low 9 bits of 0x4B400000 are zero).
__device__ __forceinline__ float exp2nf(float t) {
    float z = t + 12582912.f;             // 1.5 * 2^23, bits = 0x4B400000 + rint(t)
    float f = t - (z - 12582912.f);
    float p = fmaf(0.00133335581f, f, 0.00961812911f);
    p = fmaf(p, f, 0.0555041087f);
    p = fmaf(p, f, 0.240226507f);
    p = fmaf(p, f, 0.69314718056f);
    p = fmaf(p, f, 1.0f);
    return __int_as_float(__float_as_int(p) + (__float_as_int(z) << 23));
}
// clamped variant (alpha path only; handles -1e30)
__device__ __forceinline__ float exp2c(float t) {
    return exp2nf(fmaxf(t, -120.f));
}

#define MMA_BF16(d, a, b0, b1)                                             \
    asm volatile(                                                          \
        "mma.sync.aligned.m16n8k16.row.col.f32.bf16.bf16.f32 "            \
        "{%0,%1,%2,%3}, {%4,%5,%6,%7}, {%8,%9}, {%0,%1,%2,%3};"           \
        : "+f"((d)[0]), "+f"((d)[1]), "+f"((d)[2]), "+f"((d)[3])           \
        : "r"((a)[0]), "r"((a)[1]), "r"((a)[2]), "r"((a)[3]),              \
          "r"(b0), "r"(b1))

#define LDM_X4(r, a)                                                       \
    asm volatile("ldmatrix.sync.aligned.m8n8.x4.shared.b16 "               \
                 "{%0,%1,%2,%3}, [%4];"                                    \
                 : "=r"((r)[0]), "=r"((r)[1]), "=r"((r)[2]), "=r"((r)[3])  \
                 : "r"(a))

#define CP16(d, s)                                                         \
    asm volatile("cp.async.cg.shared.global [%0], [%1], 16;"               \
                 :: "r"(d), "l"(s))
#define CP_COMMIT() asm volatile("cp.async.commit_group;" ::: "memory")
#define CP_WAIT0()  asm volatile("cp.async.wait_group 0;" ::: "memory")
#define CP_WAIT1()  asm volatile("cp.async.wait_group 1;" ::: "memory")

__device__ __forceinline__ uint32_t sptr(const void* p) {
    return (uint32_t)__cvta_generic_to_shared(p);
}

// u8 count byte -> float via PRMT magic (byte b of word w)
__device__ __forceinline__ float cnt_f(uint32_t w, int b) {
    return __uint_as_float(__byte_perm(w, 0x4B000000u, 0x7440u | b)) - 8388608.f;
}

// ---------------------------------------------------------------------------
// fp32 -> (bf16 hi, bf16 lo) splits
// ---------------------------------------------------------------------------
__device__ __forceinline__ void split_store(__nv_bfloat16* hi, __nv_bfloat16* lo,
                                            int i, float4 v)
{
    uint32_t h0 = pack_bf16x2(v.x, v.y);
    uint32_t h1 = pack_bf16x2(v.z, v.w);
    float r0 = v.x - __uint_as_float(h0 << 16);
    float r1 = v.y - __uint_as_float(h0 & 0xffff0000u);
    float r2 = v.z - __uint_as_float(h1 << 16);
    float r3 = v.w - __uint_as_float(h1 & 0xffff0000u);
    ((uint32_t*)hi)[2 * i + 0] = h0;
    ((uint32_t*)hi)[2 * i + 1] = h1;
    ((uint32_t*)lo)[2 * i + 0] = pack_bf16x2(r0, r1);
    ((uint32_t*)lo)[2 * i + 1] = pack_bf16x2(r2, r3);
}

__global__ __launch_bounds__(256) void convert_x(const float* __restrict__ src, int n4)
{
    int i = blockIdx.x * blockDim.x + threadIdx.x;
    if (i >= n4) return;
    split_store(g_xhi, g_xlo, i, ((const float4*)src)[i]);
}

__global__ __launch_bounds__(256) void convert_w(const float* __restrict__ w0,
                                                 const float* __restrict__ w1,
                                                 const float* __restrict__ w2,
                                                 const float* __restrict__ w3,
                                                 int n4)
{
    int i = blockIdx.x * blockDim.x + threadIdx.x;
    if (i >= n4) return;
    int wi = blockIdx.y;
    const float* src = (wi == 0) ? w0 : (wi == 1) ? w1 : (wi == 2) ? w2 : w3;
    split_store(g_whi + (size_t)wi * EMB * EMB,
                g_wlo + (size_t)wi * EMB * EMB, i, ((const float4*)src)[i]);
}

// ---------------------------------------------------------------------------
// mma.sync bf16-split GEMM. mode 0 (Q) pre-scales output by QSC so attention
// scores come out of the QK MMA already in log2 units.
// ---------------------------------------------------------------------------
__global__ __launch_bounds__(128) void gemm_tc(const float* __restrict__ b0,
                                               const float* __restrict__ b1,
                                               const float* __restrict__ b2,
                                               float* __restrict__ outp,
                                               int base_mode)
{
    __shared__ __nv_bfloat16 Ah[64][PADB], Al[64][PADB];
    __shared__ __nv_bfloat16 Bh[64][PADB], Bl[64][PADB];

    int mode = base_mode + blockIdx.z;
    const float* bias = (blockIdx.z == 0) ? b0 : (blockIdx.z == 1) ? b1 : b2;
    const __nv_bfloat16* wh = g_whi + (size_t)mode * EMB * EMB;
    const __nv_bfloat16* wl = g_wlo + (size_t)mode * EMB * EMB;

    int nb = blockIdx.x * 64, mb = blockIdx.y * 64;
    int tid = threadIdx.x, w = tid >> 5, lane = tid & 31;
    int qr = lane >> 2, qc = (lane & 3) * 2;

    uint32_t sAh = sptr(&Ah[0][0]), sAl = sptr(&Al[0][0]);
    uint32_t sBh = sptr(&Bh[0][0]), sBl = sptr(&Bl[0][0]);

    int a_r = w * 16 + (lane & 7) + ((lane >> 3) & 1) * 8;
    int a_cb = ((lane >> 4) & 1) * 16;
    int b_rl = (lane & 7) + ((lane >> 4) & 1) * 8;
    int b_cb = ((lane >> 3) & 1) * 16;

    float acc[8][4];
    #pragma unroll
    for (int n = 0; n < 8; n++)
        #pragma unroll
        for (int j = 0; j < 4; j++) acc[n][j] = 0.f;

    for (int kc = 0; kc < EMB / 64; kc++) {
        __syncthreads();
        #pragma unroll
        for (int i = 0; i < 4; i++) {
            int idx = tid + i * 128;
            int r = idx >> 3, cb = (idx & 7) * 16;
            const char* ga = (const char*)(g_xhi + (size_t)(mb + r) * EMB + kc * 64) + cb;
            const char* gal = (const char*)(g_xlo + (size_t)(mb + r) * EMB + kc * 64) + cb;
            const char* gb = (const char*)(wh + (size_t)(nb + r) * EMB + kc * 64) + cb;
            const char* gbl = (const char*)(wl + (size_t)(nb + r) * EMB + kc * 64) + cb;
            uint32_t so = (uint32_t)(r * (PADB * 2) + cb);
            CP16(sAh + so, ga);
            CP16(sAl + so, gal);
            CP16(sBh + so, gb);
            CP16(sBl + so, gbl);
        }
        CP_COMMIT();
        CP_WAIT0();
        __syncthreads();

        #pragma unroll
        for (int t = 0; t < 4; t++) {
            uint32_t ah[4], al[4];
            uint32_t aoff = (uint32_t)(a_r * (PADB * 2) + t * 32 + a_cb);
            LDM_X4(ah, sAh + aoff);
            LDM_X4(al, sAl + aoff);
            #pragma unroll
            for (int nbk = 0; nbk < 4; nbk++) {
                uint32_t kh[4], kl[4];
                uint32_t boff = (uint32_t)((nbk * 16 + b_rl) * (PADB * 2) + t * 32 + b_cb);
                LDM_X4(kh, sBh + boff);
                LDM_X4(kl, sBl + boff);
                MMA_BF16(acc[2 * nbk], ah, kh[0], kh[1]);
                MMA_BF16(acc[2 * nbk], ah, kl[0], kl[1]);
                MMA_BF16(acc[2 * nbk], al, kh[0], kh[1]);
                MMA_BF16(acc[2 * nbk + 1], ah, kh[2], kh[3]);
                MMA_BF16(acc[2 * nbk + 1], ah, kl[2], kl[3]);
                MMA_BF16(acc[2 * nbk + 1], al, kh[2], kh[3]);
            }
        }
    }

    int r0 = mb + w * 16 + qr;
    if (mode == 3) {
        #pragma unroll
        for (int n = 0; n < 8; n++) {
            int col = nb + n * 8 + qc;
            float2 v0 = {acc[n][0] + bias[col], acc[n][1] + bias[col + 1]};
            float2 v1 = {acc[n][2] + bias[col], acc[n][3] + bias[col + 1]};
            *(float2*)(outp + (size_t)r0 * EMB + col) = v0;
            *(float2*)(outp + (size_t)(r0 + 8) * EMB + col) = v1;
        }
    } else if (mode == 2) {
        int hh = blockIdx.x;
        #pragma unroll
        for (int n = 0; n < 8; n++) {
            int d = n * 8 + qc;
            float bb0 = bias[nb + d], bb1 = bias[nb + d + 1];
            #pragma unroll
            for (int half = 0; half < 2; half++) {
                float v0 = acc[n][half * 2 + 0] + bb0;
                float v1 = acc[n][half * 2 + 1] + bb1;
                int tok = r0 + half * 8;
                uint32_t ph = pack_bf16x2(v0, v1);
                float e0 = v0 - __uint_as_float(ph << 16);
                float e1 = v1 - __uint_as_float(ph & 0xffff0000u);
                uint32_t pe = pack_bf16x2(e0, e1);
                size_t o0 = ((size_t)hh * HD + d) * NTOK + tok;
                size_t o1 = ((size_t)hh * HD + d + 1) * NTOK + tok;
                g_vthi[o0] = __ushort_as_bfloat16((unsigned short)(ph & 0xffffu));
                g_vthi[o1] = __ushort_as_bfloat16((unsigned short)(ph >> 16));
                g_vtlo[o0] = __ushort_as_bfloat16((unsigned short)(pe & 0xffffu));
                g_vtlo[o1] = __ushort_as_bfloat16((unsigned short)(pe >> 16));
            }
        }
    } else {
        __nv_bfloat16* dh = (mode == 0) ? g_qhi : g_khi;
        __nv_bfloat16* dl = (mode == 0) ? g_qlo : g_klo;
        float sc = (mode == 0) ? QSC : 1.0f;
        int hh = blockIdx.x;
        #pragma unroll
        for (int n = 0; n < 8; n++) {
            int d = n * 8 + qc;
            float bb0 = bias[nb + d], bb1 = bias[nb + d + 1];
            #pragma unroll
            for (int half = 0; half < 2; half++) {
                float v0 = (acc[n][half * 2 + 0] + bb0) * sc;
                float v1 = (acc[n][half * 2 + 1] + bb1) * sc;
                uint32_t ph = pack_bf16x2(v0, v1);
                float e0 = v0 - __uint_as_float(ph << 16);
                float e1 = v1 - __uint_as_float(ph & 0xffff0000u);
                size_t off = ((size_t)hh * NTOK + r0 + half * 8) * HD + d;
                *(uint32_t*)(dh + off) = ph;
                *(uint32_t*)(dl + off) = pack_bf16x2(e0, e1);
            }
        }
    }
}

// ---------------------------------------------------------------------------
// Tensor-core flash attention, software-pipelined (structure = R13 build).
// Scores arrive in log2 units (Q pre-scaled). PV is 2-pass (P-hi only),
// l sums the bf16-rounded p's. Bias counts stored transposed:
// bct[row][q*8 + n] for col = n*8 + q -> 2x LDS.128 per thread per tile.
// ---------------------------------------------------------------------------
#define AT_K(b)  ((uint32_t)(b) * 18432u)
#define AT_VH    36864u
#define AT_VL    46080u
#define AT_BC    55296
#define AT_SIM   63488
#define AT_SMEM  66048

__global__ void __launch_bounds__(128, 3) attn_tc(const int* __restrict__ sim)
{
    extern __shared__ char smx[];
    uint32_t sb = sptr(smx);
    unsigned char (*bc)[64][64] = (unsigned char (*)[64][64])(smx + AT_BC);
    int* sims = (int*)(smx + AT_SIM);

    int h = blockIdx.y, i0 = blockIdx.x * 64;
    int tid = threadIdx.x, w = tid >> 5, lane = tid & 31;
    int qr = lane >> 2, qc = (lane & 3) * 2;

    for (int t = tid; t < 640; t += 128) sims[t] = sim[(size_t)i0 * 10 + t];

    // Persistent Q fragments from global
    uint32_t qh[4][4], ql[4][4];
    {
        const __nv_bfloat16* qbh = g_qhi + ((size_t)h * NTOK + i0 + w * 16) * HD;
        const __nv_bfloat16* qbl = g_qlo + ((size_t)h * NTOK + i0 + w * 16) * HD;
        #pragma unroll
        for (int t = 0; t < 4; t++)
            #pragma unroll
            for (int j = 0; j < 4; j++) {
                int r = qr + (j & 1) * 8;
                int c = t * 16 + qc + (j >> 1) * 8;
                qh[t][j] = *(const uint32_t*)(qbh + (size_t)r * HD + c);
                ql[t][j] = *(const uint32_t*)(qbl + (size_t)r * HD + c);
            }
    }

    const __nv_bfloat16* kbh = g_khi + (size_t)h * NTOK * HD;
    const __nv_bfloat16* kbl = g_klo + (size_t)h * NTOK * HD;
    const __nv_bfloat16* vbh = g_vthi + (size_t)h * HD * NTOK;
    const __nv_bfloat16* vbl = g_vtlo + (size_t)h * HD * NTOK;

    int b_rl = (lane & 7) + ((lane >> 4) & 1) * 8;
    int b_cb = ((lane >> 3) & 1) * 16;

    auto issueK = [&](int kt) {
        uint32_t off = sb + AT_K(kt & 1);
        int j0 = kt * 64;
        #pragma unroll
        for (int i = 0; i < 4; i++) {
            int idx = tid + i * 128;
            int r = idx >> 3, cb = (idx & 7) * 16;
            uint32_t so = (uint32_t)(r * (PADB * 2) + cb);
            CP16(off + so,        (const char*)(kbh + (size_t)(j0 + r) * HD) + cb);
            CP16(off + 9216 + so, (const char*)(kbl + (size_t)(j0 + r) * HD) + cb);
        }
        CP_COMMIT();
    };
    auto issueV = [&](int kt) {
        int j0 = kt * 64;
        #pragma unroll
        for (int i = 0; i < 4; i++) {
            int idx = tid + i * 128;
            int r = idx >> 3, cb = (idx & 7) * 16;
            uint32_t so = (uint32_t)(r * (PADB * 2) + cb);
            CP16(sb + AT_VH + so, (const char*)(vbh + (size_t)r * NTOK + j0) + cb);
            CP16(sb + AT_VL + so, (const char*)(vbl + (size_t)r * NTOK + j0) + cb);
        }
        CP_COMMIT();
    };

    float o[8][4];
    #pragma unroll
    for (int n = 0; n < 8; n++)
        #pragma unroll
        for (int j = 0; j < 4; j++) o[n][j] = 0.f;
    float m0 = -1e30f, m1 = -1e30f, l0 = 0.f, l1 = 0.f;
    int br0 = w * 16 + qr, br1 = br0 + 8;

    const int NT = NTOK / 64;

    // Prologue
    issueK(0);
    for (int idx = tid; idx < 512; idx += 128)
        ((uint4*)(smx + AT_BC))[idx] = make_uint4(0u, 0u, 0u, 0u);
    __syncthreads();
    if (tid < 64) {
        #pragma unroll
        for (int s5 = 0; s5 < 10; s5++) {
            int rel = sims[tid * 10 + s5];
            if ((unsigned)rel < 64u) (*bc)[tid][(rel & 7) * 8 + (rel >> 3)]++;
        }
    }

    for (int kt = 0; kt < NT; kt++) {
        CP_WAIT0();
        __syncthreads();       // B1

        issueV(kt);

        {
            uint4* bz = (uint4*)(smx + AT_BC + ((kt + 1) & 1) * 4096);
            for (int idx = tid; idx < 256; idx += 128)
                bz[idx] = make_uint4(0u, 0u, 0u, 0u);
        }

        // ---- S = Q K^T (3-pass bf16 split); scores in log2 units ----
        uint32_t sKh = sb + AT_K(kt & 1), sKl = sKh + 9216;
        float s[8][4];
        #pragma unroll
        for (int n = 0; n < 8; n++)
            #pragma unroll
            for (int j = 0; j < 4; j++) s[n][j] = 0.f;
        #pragma unroll
        for (int t = 0; t < 4; t++) {
            #pragma unroll
            for (int nbk = 0; nbk < 4; nbk++) {
                uint32_t kh[4], kl[4];
                uint32_t boff = (uint32_t)((nbk * 16 + b_rl) * (PADB * 2) + t * 32 + b_cb);
                LDM_X4(kh, sKh + boff);
                LDM_X4(kl, sKl + boff);
                MMA_BF16(s[2 * nbk], qh[t], kh[0], kh[1]);
                MMA_BF16(s[2 * nbk + 1], qh[t], kh[2], kh[3]);
                MMA_BF16(s[2 * nbk], qh[t], kl[0], kl[1]);
                MMA_BF16(s[2 * nbk + 1], qh[t], kl[2], kl[3]);
                MMA_BF16(s[2 * nbk], ql[t], kh[0], kh[1]);
                MMA_BF16(s[2 * nbk + 1], ql[t], kh[2], kh[3]);
            }
        }

        if (kt + 1 < NT) issueK(kt + 1);

        // ---- bias add (transposed u8 counts, 2x LDS.128) + max ----
        const unsigned char* bcc = (const unsigned char*)(smx + AT_BC + (kt & 1) * 4096);
        uint4 c0 = *(const uint4*)(bcc + br0 * 64 + qc * 8);
        uint4 c1 = *(const uint4*)(bcc + br1 * 64 + qc * 8);
        float mx0 = -1e30f, mx1 = -1e30f;
        #pragma unroll
        for (int n = 0; n < 8; n++) {
            int b = n & 3;
            uint32_t w0 = (n < 4) ? c0.x : c0.y;
            uint32_t w1 = (n < 4) ? c0.z : c0.w;
            uint32_t w2 = (n < 4) ? c1.x : c1.y;
            uint32_t w3 = (n < 4) ? c1.z : c1.w;
            s[n][0] = fmaf(cnt_f(w0, b), L2E, s[n][0]);
            s[n][1] = fmaf(cnt_f(w1, b), L2E, s[n][1]);
            s[n][2] = fmaf(cnt_f(w2, b), L2E, s[n][2]);
            s[n][3] = fmaf(cnt_f(w3, b), L2E, s[n][3]);
            mx0 = fmaxf(mx0, fmaxf(s[n][0], s[n][1]));
            mx1 = fmaxf(mx1, fmaxf(s[n][2], s[n][3]));
        }
        #pragma unroll
        for (int off = 1; off <= 2; off <<= 1) {
            mx0 = fmaxf(mx0, __shfl_xor_sync(0xffffffffu, mx0, off));
            mx1 = fmaxf(mx1, __shfl_xor_sync(0xffffffffu, mx1, off));
        }
        float mn0 = fmaxf(m0, mx0), mn1 = fmaxf(m1, mx1);

        // ---- exps; l sums the bf16-ROUNDED p (consistent with PV) ----
        float rs0 = 0.f, rs1 = 0.f;
        uint32_t pa[4][4];
        #pragma unroll
        for (int n = 0; n < 8; n++) {
            float p0 = exp2nf(s[n][0] - mn0);
            float p1 = exp2nf(s[n][1] - mn0);
            float p2 = exp2nf(s[n][2] - mn1);
            float p3 = exp2nf(s[n][3] - mn1);
            uint32_t hp01 = pack_bf16x2(p0, p1);
            uint32_t hp23 = pack_bf16x2(p2, p3);
            rs0 += __uint_as_float(hp01 << 16) + __uint_as_float(hp01 & 0xffff0000u);
            rs1 += __uint_as_float(hp23 << 16) + __uint_as_float(hp23 & 0xffff0000u);
            int t = n >> 1, half = (n & 1) * 2;
            pa[t][half + 0] = hp01;
            pa[t][half + 1] = hp23;
        }
        #pragma unroll
        for (int off = 1; off <= 2; off <<= 1) {
            rs0 += __shfl_xor_sync(0xffffffffu, rs0, off);
            rs1 += __shfl_xor_sync(0xffffffffu, rs1, off);
        }

        if (__all_sync(0xffffffffu, (mn0 == m0) & (mn1 == m1))) {
            l0 += rs0;
            l1 += rs1;
        } else {
            float a0 = exp2c(m0 - mn0), a1 = exp2c(m1 - mn1);
            l0 = l0 * a0 + rs0;
            l1 = l1 * a1 + rs1;
            m0 = mn0;
            m1 = mn1;
            #pragma unroll
            for (int n = 0; n < 8; n++) {
                o[n][0] *= a0; o[n][1] *= a0;
                o[n][2] *= a1; o[n][3] *= a1;
            }
        }

        // ---- wait V_kt ----
        if (kt + 1 < NT) { CP_WAIT1(); } else { CP_WAIT0(); }
        __syncthreads();       // B2

        if (kt + 1 < NT && tid < 64) {
            int jn = (kt + 1) * 64;
            #pragma unroll
            for (int s5 = 0; s5 < 10; s5++) {
                int rel = sims[tid * 10 + s5] - jn;
                if ((unsigned)rel < 64u)
                    bc[(kt + 1) & 1][tid][(rel & 7) * 8 + (rel >> 3)]++;
            }
        }

        // ---- O += P V (2-pass: P-hi x V-hi + P-hi x V-lo) ----
        uint32_t sVh = sb + AT_VH, sVl = sb + AT_VL;
        #pragma unroll
        for (int t = 0; t < 4; t++) {
            #pragma unroll
            for (int nbk = 0; nbk < 4; nbk++) {
                uint32_t vh[4], vl[4];
                uint32_t boff = (uint32_t)((nbk * 16 + b_rl) * (PADB * 2) + t * 32 + b_cb);
                LDM_X4(vh, sVh + boff);
                LDM_X4(vl, sVl + boff);
                MMA_BF16(o[2 * nbk], pa[t], vh[0], vh[1]);
                MMA_BF16(o[2 * nbk + 1], pa[t], vh[2], vh[3]);
                MMA_BF16(o[2 * nbk], pa[t], vl[0], vl[1]);
                MMA_BF16(o[2 * nbk + 1], pa[t], vl[2], vl[3]);
            }
        }
    }

    // Fused epilogue: split-store O directly as O-projection input
    float il0 = 1.f / l0, il1 = 1.f / l1;
    #pragma unroll
    for (int n = 0; n < 8; n++) {
        int col = h * HD + n * 8 + qc;
        float v0 = o[n][0] * il0, v1 = o[n][1] * il0;
        float v2 = o[n][2] * il1, v3 = o[n][3] * il1;
        uint32_t h0 = pack_bf16x2(v0, v1);
        uint32_t h1 = pack_bf16x2(v2, v3);
        float e0 = v0 - __uint_as_float(h0 << 16);
        float e1 = v1 - __uint_as_float(h0 & 0xffff0000u);
        float e2 = v2 - __uint_as_float(h1 << 16);
        float e3 = v3 - __uint_as_float(h1 & 0xffff0000u);
        size_t o0 = (size_t)(i0 + br0) * EMB + col;
        size_t o1 = (size_t)(i0 + br1) * EMB + col;
        *(uint32_t*)(g_xhi + o0) = h0;
        *(uint32_t*)(g_xlo + o0) = pack_bf16x2(e0, e1);
        *(uint32_t*)(g_xhi + o1) = h1;
        *(uint32_t*)(g_xlo + o1) = pack_bf16x2(e2, e3);
    }
}

// ---------------------------------------------------------------------------
extern "C" void kernel_launch(void* const* d_in, const int* in_sizes, int n_in,
                              void* d_out, int out_size)
{
    const float* x   = (const float*)d_in[0];
    const int*   sim = (const int*)d_in[1];
    const float* Wq  = (const float*)d_in[2];
    const float* bq  = (const float*)d_in[3];
    const float* Wk  = (const float*)d_in[4];
    const float* bk  = (const float*)d_in[5];
    const float* Wv  = (const float*)d_in[6];
    const float* bv  = (const float*)d_in[7];
    const float* Wo  = (const float*)d_in[8];
    const float* bo  = (const float*)d_in[9];
    float* out = (float*)d_out;

    cudaFuncSetAttribute(attn_tc, cudaFuncAttributeMaxDynamicSharedMemorySize, AT_SMEM);

    const int n4x = NTOK * EMB / 4;
    const int n4w = EMB * EMB / 4;

    convert_x<<<n4x / 256, 256>>>(x, n4x);
    convert_w<<<dim3(n4w / 256, 4), 256>>>(Wq, Wk, Wv, Wo, n4w);

    gemm_tc<<<dim3(EMB / 64, NTOK / 64, 3), 128>>>(bq, bk, bv, nullptr, 0);

    attn_tc<<<dim3(NTOK / 64, NH), 128, AT_SMEM>>>(sim);

    gemm_tc<<<dim3(EMB / 64, NTOK / 64, 1), 128>>>(bo, nullptr, nullptr, out, 3);
}

// round 15
// speedup vs baseline: 1.3417x; 1.0002x over previous
#include <cuda_runtime.h>
#include <cuda_bf16.h>
#include <cuda_fp16.h>
#include <cstdint>

#define NTOK 4096
#define EMB  768
#define NH   12
#define HD   64
#define PADB 72
#define L2E  1.4426950408889634f
#define QSC  (0.125f * 1.4426950408889634f)

// ---------------------------------------------------------------------------
// Scratch (allocation-free device globals)
// ---------------------------------------------------------------------------
__device__ __align__(16) __nv_bfloat16 g_xhi[NTOK * EMB];
__device__ __align__(16) __nv_bfloat16 g_xlo[NTOK * EMB];
__device__ __align__(16) __nv_bfloat16 g_whi[4 * EMB * EMB];
__device__ __align__(16) __nv_bfloat16 g_wlo[4 * EMB * EMB];
__device__ __align__(16) __nv_bfloat16 g_qhi[NH * NTOK * HD];
__device__ __align__(16) __nv_bfloat16 g_qlo[NH * NTOK * HD];
__device__ __align__(16) __nv_bfloat16 g_khi[NH * NTOK * HD];
__device__ __align__(16) __nv_bfloat16 g_klo[NH * NTOK * HD];
__device__ __align__(16) __half g_vthi[NH * HD * NTOK];   // fp16 V (transposed)
__device__ __align__(16) __half g_vtlo[NH * HD * NTOK];   // fp16 V residual

// ---------------------------------------------------------------------------
// Helpers
// ---------------------------------------------------------------------------
__device__ __forceinline__ uint32_t pack_bf16x2(float lo, float hi) {
    uint32_t r;
    asm("cvt.rn.bf16x2.f32 %0, %1, %2;" : "=r"(r) : "f"(hi), "f"(lo));
    return r;
}
__device__ __forceinline__ uint32_t pack_f16x2(float lo, float hi) {
    __half2 h = __floats2half2_rn(lo, hi);   // lo -> low 16 bits
    return *reinterpret_cast<uint32_t*>(&h);
}
__device__ __forceinline__ float2 f16x2_to_f32(uint32_t u) {
    __half2 h = *reinterpret_cast<__half2*>(&u);
    return __half22float2(h);
}

// exp2 for t in [-~60, 0]; NO clamp. exp2nf(0) == 1.0 exactly.
__device__ __forceinline__ float exp2nf(float t) {
    float z = t + 12582912.f;             // 1.5 * 2^23
    float f = t - (z - 12582912.f);
    float p = fmaf(0.00133335581f, f, 0.00961812911f);
    p = fmaf(p, f, 0.0555041087f);
    p = fmaf(p, f, 0.240226507f);
    p = fmaf(p, f, 0.69314718056f);
    p = fmaf(p, f, 1.0f);
    return __int_as_float(__float_as_int(p) + (__float_as_int(z) << 23));
}
// clamped variant (alpha path only; handles -1e30)
__device__ __forceinline__ float exp2c(float t) {
    return exp2nf(fmaxf(t, -120.f));
}

#define MMA_BF16(d, a, b0, b1)                                             \
    asm volatile(                                                          \
        "mma.sync.aligned.m16n8k16.row.col.f32.bf16.bf16.f32 "            \
        "{%0,%1,%2,%3}, {%4,%5,%6,%7}, {%8,%9}, {%0,%1,%2,%3};"           \
        : "+f"((d)[0]), "+f"((d)[1]), "+f"((d)[2]), "+f"((d)[3])           \
        : "r"((a)[0]), "r"((a)[1]), "r"((a)[2]), "r"((a)[3]),              \
          "r"(b0), "r"(b1))

#define MMA_F16(d, a, b0, b1)                                              \
    asm volatile(                                                          \
        "mma.sync.aligned.m16n8k16.row.col.f32.f16.f16.f32 "              \
        "{%0,%1,%2,%3}, {%4,%5,%6,%7}, {%8,%9}, {%0,%1,%2,%3};"           \
        : "+f"((d)[0]), "+f"((d)[1]), "+f"((d)[2]), "+f"((d)[3])           \
        : "r"((a)[0]), "r"((a)[1]), "r"((a)[2]), "r"((a)[3]),              \
          "r"(b0), "r"(b1))

#define LDM_X4(r, a)                                                       \
    asm volatile("ldmatrix.sync.aligned.m8n8.x4.shared.b16 "               \
                 "{%0,%1,%2,%3}, [%4];"                                    \
                 : "=r"((r)[0]), "=r"((r)[1]), "=r"((r)[2]), "=r"((r)[3])  \
                 : "r"(a))

#define CP16(d, s)                                                         \
    asm volatile("cp.async.cg.shared.global [%0], [%1], 16;"               \
                 :: "r"(d), "l"(s))
#define CP_COMMIT() asm volatile("cp.async.commit_group;" ::: "memory")
#define CP_WAIT0()  asm volatile("cp.async.wait_group 0;" ::: "memory")
#define CP_WAIT1()  asm volatile("cp.async.wait_group 1;" ::: "memory")

__device__ __forceinline__ uint32_t sptr(const void* p) {
    return (uint32_t)__cvta_generic_to_shared(p);
}

// u8 count byte -> float via PRMT magic (byte b of word w)
__device__ __forceinline__ float cnt_f(uint32_t w, int b) {
    return __uint_as_float(__byte_perm(w, 0x4B000000u, 0x7440u | b)) - 8388608.f;
}

// ---------------------------------------------------------------------------
// fp32 -> (bf16 hi, bf16 lo) splits
// ---------------------------------------------------------------------------
__device__ __forceinline__ void split_store(__nv_bfloat16* hi, __nv_bfloat16* lo,
                                            int i, float4 v)
{
    uint32_t h0 = pack_bf16x2(v.x, v.y);
    uint32_t h1 = pack_bf16x2(v.z, v.w);
    float r0 = v.x - __uint_as_float(h0 << 16);
    float r1 = v.y - __uint_as_float(h0 & 0xffff0000u);
    float r2 = v.z - __uint_as_float(h1 << 16);
    float r3 = v.w - __uint_as_float(h1 & 0xffff0000u);
    ((uint32_t*)hi)[2 * i + 0] = h0;
    ((uint32_t*)hi)[2 * i + 1] = h1;
    ((uint32_t*)lo)[2 * i + 0] = pack_bf16x2(r0, r1);
    ((uint32_t*)lo)[2 * i + 1] = pack_bf16x2(r2, r3);
}

__global__ __launch_bounds__(256) void convert_x(const float* __restrict__ src, int n4)
{
    int i = blockIdx.x * blockDim.x + threadIdx.x;
    if (i >= n4) return;
    split_store(g_xhi, g_xlo, i, ((const float4*)src)[i]);
}

__global__ __launch_bounds__(256) void convert_w(const float* __restrict__ w0,
                                                 const float* __restrict__ w1,
                                                 const float* __restrict__ w2,
                                                 const float* __restrict__ w3,
                                                 int n4)
{
    int i = blockIdx.x * blockDim.x + threadIdx.x;
    if (i >= n4) return;
    int wi = blockIdx.y;
    const float* src = (wi == 0) ? w0 : (wi == 1) ? w1 : (wi == 2) ? w2 : w3;
    split_store(g_whi + (size_t)wi * EMB * EMB,
                g_wlo + (size_t)wi * EMB * EMB, i, ((const float4*)src)[i]);
}

// ---------------------------------------------------------------------------
// mma.sync bf16-split GEMM. mode 0 (Q) pre-scales output by QSC (log2 domain).
// mode 2 (V) emits fp16 hi/lo TRANSPOSED [h][d][tok].
// ---------------------------------------------------------------------------
__global__ __launch_bounds__(128) void gemm_tc(const float* __restrict__ b0,
                                               const float* __restrict__ b1,
                                               const float* __restrict__ b2,
                                               float* __restrict__ outp,
                                               int base_mode)
{
    __shared__ __nv_bfloat16 Ah[64][PADB], Al[64][PADB];
    __shared__ __nv_bfloat16 Bh[64][PADB], Bl[64][PADB];

    int mode = base_mode + blockIdx.z;
    const float* bias = (blockIdx.z == 0) ? b0 : (blockIdx.z == 1) ? b1 : b2;
    const __nv_bfloat16* wh = g_whi + (size_t)mode * EMB * EMB;
    const __nv_bfloat16* wl = g_wlo + (size_t)mode * EMB * EMB;

    int nb = blockIdx.x * 64, mb = blockIdx.y * 64;
    int tid = threadIdx.x, w = tid >> 5, lane = tid & 31;
    int qr = lane >> 2, qc = (lane & 3) * 2;

    uint32_t sAh = sptr(&Ah[0][0]), sAl = sptr(&Al[0][0]);
    uint32_t sBh = sptr(&Bh[0][0]), sBl = sptr(&Bl[0][0]);

    int a_r = w * 16 + (lane & 7) + ((lane >> 3) & 1) * 8;
    int a_cb = ((lane >> 4) & 1) * 16;
    int b_rl = (lane & 7) + ((lane >> 4) & 1) * 8;
    int b_cb = ((lane >> 3) & 1) * 16;

    float acc[8][4];
    #pragma unroll
    for (int n = 0; n < 8; n++)
        #pragma unroll
        for (int j = 0; j < 4; j++) acc[n][j] = 0.f;

    for (int kc = 0; kc < EMB / 64; kc++) {
        __syncthreads();
        #pragma unroll
        for (int i = 0; i < 4; i++) {
            int idx = tid + i * 128;
            int r = idx >> 3, cb = (idx & 7) * 16;
            const char* ga = (const char*)(g_xhi + (size_t)(mb + r) * EMB + kc * 64) + cb;
            const char* gal = (const char*)(g_xlo + (size_t)(mb + r) * EMB + kc * 64) + cb;
            const char* gb = (const char*)(wh + (size_t)(nb + r) * EMB + kc * 64) + cb;
            const char* gbl = (const char*)(wl + (size_t)(nb + r) * EMB + kc * 64) + cb;
            uint32_t so = (uint32_t)(r * (PADB * 2) + cb);
            CP16(sAh + so, ga);
            CP16(sAl + so, gal);
            CP16(sBh + so, gb);
            CP16(sBl + so, gbl);
        }
        CP_COMMIT();
        CP_WAIT0();
        __syncthreads();

        #pragma unroll
        for (int t = 0; t < 4; t++) {
            uint32_t ah[4], al[4];
            uint32_t aoff = (uint32_t)(a_r * (PADB * 2) + t * 32 + a_cb);
            LDM_X4(ah, sAh + aoff);
            LDM_X4(al, sAl + aoff);
            #pragma unroll
            for (int nbk = 0; nbk < 4; nbk++) {
                uint32_t kh[4], kl[4];
                uint32_t boff = (uint32_t)((nbk * 16 + b_rl) * (PADB * 2) + t * 32 + b_cb);
                LDM_X4(kh, sBh + boff);
                LDM_X4(kl, sBl + boff);
                MMA_BF16(acc[2 * nbk], ah, kh[0], kh[1]);
                MMA_BF16(acc[2 * nbk], ah, kl[0], kl[1]);
                MMA_BF16(acc[2 * nbk], al, kh[0], kh[1]);
                MMA_BF16(acc[2 * nbk + 1], ah, kh[2], kh[3]);
                MMA_BF16(acc[2 * nbk + 1], ah, kl[2], kl[3]);
                MMA_BF16(acc[2 * nbk + 1], al, kh[2], kh[3]);
            }
        }
    }

    int r0 = mb + w * 16 + qr;
    if (mode == 3) {
        #pragma unroll
        for (int n = 0; n < 8; n++) {
            int col = nb + n * 8 + qc;
            float2 v0 = {acc[n][0] + bias[col], acc[n][1] + bias[col + 1]};
            float2 v1 = {acc[n][2] + bias[col], acc[n][3] + bias[col + 1]};
            *(float2*)(outp + (size_t)r0 * EMB + col) = v0;
            *(float2*)(outp + (size_t)(r0 + 8) * EMB + col) = v1;
        }
    } else if (mode == 2) {
        // V: fp16 hi/lo, TRANSPOSED into g_vt [h][d][tok]
        int hh = blockIdx.x;
        #pragma unroll
        for (int n = 0; n < 8; n++) {
            int d = n * 8 + qc;
            float bb0 = bias[nb + d], bb1 = bias[nb + d + 1];
            #pragma unroll
            for (int half = 0; half < 2; half++) {
                float v0 = acc[n][half * 2 + 0] + bb0;
                float v1 = acc[n][half * 2 + 1] + bb1;
                int tok = r0 + half * 8;
                __half h0 = __float2half_rn(v0);
                __half h1 = __float2half_rn(v1);
                size_t o0 = ((size_t)hh * HD + d) * NTOK + tok;
                size_t o1 = ((size_t)hh * HD + d + 1) * NTOK + tok;
                g_vthi[o0] = h0;
                g_vthi[o1] = h1;
                g_vtlo[o0] = __float2half_rn(v0 - __half2float(h0));
                g_vtlo[o1] = __float2half_rn(v1 - __half2float(h1));
            }
        }
    } else {
        __nv_bfloat16* dh = (mode == 0) ? g_qhi : g_khi;
        __nv_bfloat16* dl = (mode == 0) ? g_qlo : g_klo;
        float sc = (mode == 0) ? QSC : 1.0f;
        int hh = blockIdx.x;
        #pragma unroll
        for (int n = 0; n < 8; n++) {
            int d = n * 8 + qc;
            float bb0 = bias[nb + d], bb1 = bias[nb + d + 1];
            #pragma unroll
            for (int half = 0; half < 2; half++) {
                float v0 = (acc[n][half * 2 + 0] + bb0) * sc;
                float v1 = (acc[n][half * 2 + 1] + bb1) * sc;
                uint32_t ph = pack_bf16x2(v0, v1);
                float e0 = v0 - __uint_as_float(ph << 16);
                float e1 = v1 - __uint_as_float(ph & 0xffff0000u);
                size_t off = ((size_t)hh * NTOK + r0 + half * 8) * HD + d;
                *(uint32_t*)(dh + off) = ph;
                *(uint32_t*)(dl + off) = pack_bf16x2(e0, e1);
            }
        }
    }
}

// ---------------------------------------------------------------------------
// Tensor-core flash attention, software-pipelined (structure = R13/R14 build).
// QK: bf16 3-pass, scores in log2 units. PV: fp16 2-pass (P fp16-rounded,
// V fp16 hi + fp16 lo); l sums the fp16-ROUNDED p's so weights normalize
// exactly. Bias counts transposed u8 -> 2x LDS.128 + PRMT.
// ---------------------------------------------------------------------------
#define AT_K(b)  ((uint32_t)(b) * 18432u)
#define AT_VH    36864u
#define AT_VL    46080u
#define AT_BC    55296
#define AT_SIM   63488
#define AT_SMEM  66048

__global__ void __launch_bounds__(128, 3) attn_tc(const int* __restrict__ sim)
{
    extern __shared__ char smx[];
    uint32_t sb = sptr(smx);
    unsigned char (*bc)[64][64] = (unsigned char (*)[64][64])(smx + AT_BC);
    int* sims = (int*)(smx + AT_SIM);

    int h = blockIdx.y, i0 = blockIdx.x * 64;
    int tid = threadIdx.x, w = tid >> 5, lane = tid & 31;
    int qr = lane >> 2, qc = (lane & 3) * 2;

    for (int t = tid; t < 640; t += 128) sims[t] = sim[(size_t)i0 * 10 + t];

    // Persistent Q fragments from global
    uint32_t qh[4][4], ql[4][4];
    {
        const __nv_bfloat16* qbh = g_qhi + ((size_t)h * NTOK + i0 + w * 16) * HD;
        const __nv_bfloat16* qbl = g_qlo + ((size_t)h * NTOK + i0 + w * 16) * HD;
        #pragma unroll
        for (int t = 0; t < 4; t++)
            #pragma unroll
            for (int j = 0; j < 4; j++) {
                int r = qr + (j & 1) * 8;
                int c = t * 16 + qc + (j >> 1) * 8;
                qh[t][j] = *(const uint32_t*)(qbh + (size_t)r * HD + c);
                ql[t][j] = *(const uint32_t*)(qbl + (size_t)r * HD + c);
            }
    }

    const __nv_bfloat16* kbh = g_khi + (size_t)h * NTOK * HD;
    const __nv_bfloat16* kbl = g_klo + (size_t)h * NTOK * HD;
    const __half* vbh = g_vthi + (size_t)h * HD * NTOK;
    const __half* vbl = g_vtlo + (size_t)h * HD * NTOK;

    int b_rl = (lane & 7) + ((lane >> 4) & 1) * 8;
    int b_cb = ((lane >> 3) & 1) * 16;

    auto issueK = [&](int kt) {
        uint32_t off = sb + AT_K(kt & 1);
        int j0 = kt * 64;
        #pragma unroll
        for (int i = 0; i < 4; i++) {
            int idx = tid + i * 128;
            int r = idx >> 3, cb = (idx & 7) * 16;
            uint32_t so = (uint32_t)(r * (PADB * 2) + cb);
            CP16(off + so,        (const char*)(kbh + (size_t)(j0 + r) * HD) + cb);
            CP16(off + 9216 + so, (const char*)(kbl + (size_t)(j0 + r) * HD) + cb);
        }
        CP_COMMIT();
    };
    auto issueV = [&](int kt) {
        int j0 = kt * 64;
        #pragma unroll
        for (int i = 0; i < 4; i++) {
            int idx = tid + i * 128;
            int r = idx >> 3, cb = (idx & 7) * 16;
            uint32_t so = (uint32_t)(r * (PADB * 2) + cb);
            CP16(sb + AT_VH + so, (const char*)(vbh + (size_t)r * NTOK + j0) + cb);
            CP16(sb + AT_VL + so, (const char*)(vbl + (size_t)r * NTOK + j0) + cb);
        }
        CP_COMMIT();
    };

    float o[8][4];
    #pragma unroll
    for (int n = 0; n < 8; n++)
        #pragma unroll
        for (int j = 0; j < 4; j++) o[n][j] = 0.f;
    float m0 = -1e30f, m1 = -1e30f, l0 = 0.f, l1 = 0.f;
    int br0 = w * 16 + qr, br1 = br0 + 8;

    const int NT = NTOK / 64;

    // Prologue
    issueK(0);
    for (int idx = tid; idx < 512; idx += 128)
        ((uint4*)(smx + AT_BC))[idx] = make_uint4(0u, 0u, 0u, 0u);
    __syncthreads();
    if (tid < 64) {
        #pragma unroll
        for (int s5 = 0; s5 < 10; s5++) {
            int rel = sims[tid * 10 + s5];
            if ((unsigned)rel < 64u) (*bc)[tid][(rel & 7) * 8 + (rel >> 3)]++;
        }
    }

    for (int kt = 0; kt < NT; kt++) {
        CP_WAIT0();
        __syncthreads();       // B1

        issueV(kt);

        {
            uint4* bz = (uint4*)(smx + AT_BC + ((kt + 1) & 1) * 4096);
            for (int idx = tid; idx < 256; idx += 128)
                bz[idx] = make_uint4(0u, 0u, 0u, 0u);
        }

        // ---- S = Q K^T (3-pass bf16 split); scores in log2 units ----
        uint32_t sKh = sb + AT_K(kt & 1), sKl = sKh + 9216;
        float s[8][4];
        #pragma unroll
        for (int n = 0; n < 8; n++)
            #pragma unroll
            for (int j = 0; j < 4; j++) s[n][j] = 0.f;
        #pragma unroll
        for (int t = 0; t < 4; t++) {
            #pragma unroll
            for (int nbk = 0; nbk < 4; nbk++) {
                uint32_t kh[4], kl[4];
                uint32_t boff = (uint32_t)((nbk * 16 + b_rl) * (PADB * 2) + t * 32 + b_cb);
                LDM_X4(kh, sKh + boff);
                LDM_X4(kl, sKl + boff);
                MMA_BF16(s[2 * nbk], qh[t], kh[0], kh[1]);
                MMA_BF16(s[2 * nbk + 1], qh[t], kh[2], kh[3]);
                MMA_BF16(s[2 * nbk], qh[t], kl[0], kl[1]);
                MMA_BF16(s[2 * nbk + 1], qh[t], kl[2], kl[3]);
                MMA_BF16(s[2 * nbk], ql[t], kh[0], kh[1]);
                MMA_BF16(s[2 * nbk + 1], ql[t], kh[2], kh[3]);
            }
        }

        if (kt + 1 < NT) issueK(kt + 1);

        // ---- bias add (transposed u8 counts, 2x LDS.128) + max ----
        const unsigned char* bcc = (const unsigned char*)(smx + AT_BC + (kt & 1) * 4096);
        uint4 c0 = *(const uint4*)(bcc + br0 * 64 + qc * 8);
        uint4 c1 = *(const uint4*)(bcc + br1 * 64 + qc * 8);
        float mx0 = -1e30f, mx1 = -1e30f;
        #pragma unroll
        for (int n = 0; n < 8; n++) {
            int b = n & 3;
            uint32_t w0 = (n < 4) ? c0.x : c0.y;
            uint32_t w1 = (n < 4) ? c0.z : c0.w;
            uint32_t w2 = (n < 4) ? c1.x : c1.y;
            uint32_t w3 = (n < 4) ? c1.z : c1.w;
            s[n][0] = fmaf(cnt_f(w0, b), L2E, s[n][0]);
            s[n][1] = fmaf(cnt_f(w1, b), L2E, s[n][1]);
            s[n][2] = fmaf(cnt_f(w2, b), L2E, s[n][2]);
            s[n][3] = fmaf(cnt_f(w3, b), L2E, s[n][3]);
            mx0 = fmaxf(mx0, fmaxf(s[n][0], s[n][1]));
            mx1 = fmaxf(mx1, fmaxf(s[n][2], s[n][3]));
        }
        #pragma unroll
        for (int off = 1; off <= 2; off <<= 1) {
            mx0 = fmaxf(mx0, __shfl_xor_sync(0xffffffffu, mx0, off));
            mx1 = fmaxf(mx1, __shfl_xor_sync(0xffffffffu, mx1, off));
        }
        float mn0 = fmaxf(m0, mx0), mn1 = fmaxf(m1, mx1);

        // ---- exps; P rounded to fp16; l sums the fp16-ROUNDED p ----
        float rs0 = 0.f, rs1 = 0.f;
        uint32_t pa[4][4];
        #pragma unroll
        for (int n = 0; n < 8; n++) {
            float p0 = exp2nf(s[n][0] - mn0);
            float p1 = exp2nf(s[n][1] - mn0);
            float p2 = exp2nf(s[n][2] - mn1);
            float p3 = exp2nf(s[n][3] - mn1);
            uint32_t hp01 = pack_f16x2(p0, p1);
            uint32_t hp23 = pack_f16x2(p2, p3);
            float2 f01 = f16x2_to_f32(hp01);
            float2 f23 = f16x2_to_f32(hp23);
            rs0 += f01.x + f01.y;
            rs1 += f23.x + f23.y;
            int t = n >> 1, half = (n & 1) * 2;
            pa[t][half + 0] = hp01;
            pa[t][half + 1] = hp23;
        }
        #pragma unroll
        for (int off = 1; off <= 2; off <<= 1) {
            rs0 += __shfl_xor_sync(0xffffffffu, rs0, off);
            rs1 += __shfl_xor_sync(0xffffffffu, rs1, off);
        }

        if (__all_sync(0xffffffffu, (mn0 == m0) & (mn1 == m1))) {
            l0 += rs0;
            l1 += rs1;
        } else {
            float a0 = exp2c(m0 - mn0), a1 = exp2c(m1 - mn1);
            l0 = l0 * a0 + rs0;
            l1 = l1 * a1 + rs1;
            m0 = mn0;
            m1 = mn1;
            #pragma unroll
            for (int n = 0; n < 8; n++) {
                o[n][0] *= a0; o[n][1] *= a0;
                o[n][2] *= a1; o[n][3] *= a1;
            }
        }

        // ---- wait V_kt ----
        if (kt + 1 < NT) { CP_WAIT1(); } else { CP_WAIT0(); }
        __syncthreads();       // B2

        if (kt + 1 < NT && tid < 64) {
            int jn = (kt + 1) * 64;
            #pragma unroll
            for (int s5 = 0; s5 < 10; s5++) {
                int rel = sims[tid * 10 + s5] - jn;
                if ((unsigned)rel < 64u)
                    bc[(kt + 1) & 1][tid][(rel & 7) * 8 + (rel >> 3)]++;
            }
        }

        // ---- O += P V (fp16 2-pass: P x V-hi + P x V-lo) ----
        uint32_t sVh = sb + AT_VH, sVl = sb + AT_VL;
        #pragma unroll
        for (int t = 0; t < 4; t++) {
            #pragma unroll
            for (int nbk = 0; nbk < 4; nbk++) {
                uint32_t vh[4], vl[4];
                uint32_t boff = (uint32_t)((nbk * 16 + b_rl) * (PADB * 2) + t * 32 + b_cb);
                LDM_X4(vh, sVh + boff);
                LDM_X4(vl, sVl + boff);
                MMA_F16(o[2 * nbk], pa[t], vh[0], vh[1]);
                MMA_F16(o[2 * nbk + 1], pa[t], vh[2], vh[3]);
                MMA_F16(o[2 * nbk], pa[t], vl[0], vl[1]);
                MMA_F16(o[2 * nbk + 1], pa[t], vl[2], vl[3]);
            }
        }
    }

    // Fused epilogue: split-store O directly as O-projection input
    float il0 = 1.f / l0, il1 = 1.f / l1;
    #pragma unroll
    for (int n = 0; n < 8; n++) {
        int col = h * HD + n * 8 + qc;
        float v0 = o[n][0] * il0, v1 = o[n][1] * il0;
        float v2 = o[n][2] * il1, v3 = o[n][3] * il1;
        uint32_t h0 = pack_bf16x2(v0, v1);
        uint32_t h1 = pack_bf16x2(v2, v3);
        float e0 = v0 - __uint_as_float(h0 << 16);
        float e1 = v1 - __uint_as_float(h0 & 0xffff0000u);
        float e2 = v2 - __uint_as_float(h1 << 16);
        float e3 = v3 - __uint_as_float(h1 & 0xffff0000u);
        size_t o0 = (size_t)(i0 + br0) * EMB + col;
        size_t o1 = (size_t)(i0 + br1) * EMB + col;
        *(uint32_t*)(g_xhi + o0) = h0;
        *(uint32_t*)(g_xlo + o0) = pack_bf16x2(e0, e1);
        *(uint32_t*)(g_xhi + o1) = h1;
        *(uint32_t*)(g_xlo + o1) = pack_bf16x2(e2, e3);
    }
}

// ---------------------------------------------------------------------------
extern "C" void kernel_launch(void* const* d_in, const int* in_sizes, int n_in,
                              void* d_out, int out_size)
{
    const float* x   = (const float*)d_in[0];
    const int*   sim = (const int*)d_in[1];
    const float* Wq  = (const float*)d_in[2];
    const float* bq  = (const float*)d_in[3];
    const float* Wk  = (const float*)d_in[4];
    const float* bk  = (const float*)d_in[5];
    const float* Wv  = (const float*)d_in[6];
    const float* bv  = (const float*)d_in[7];
    const float* Wo  = (const float*)d_in[8];
    const float* bo  = (const float*)d_in[9];
    float* out = (float*)d_out;

    cudaFuncSetAttribute(attn_tc, cudaFuncAttributeMaxDynamicSharedMemorySize, AT_SMEM);

    const int n4x = NTOK * EMB / 4;
    const int n4w = EMB * EMB / 4;

    convert_x<<<n4x / 256, 256>>>(x, n4x);
    convert_w<<<dim3(n4w / 256, 4), 256>>>(Wq, Wk, Wv, Wo, n4w);

    gemm_tc<<<dim3(EMB / 64, NTOK / 64, 3), 128>>>(bq, bk, bv, nullptr, 0);

    attn_tc<<<dim3(NTOK / 64, NH), 128, AT_SMEM>>>(sim);

    gemm_tc<<<dim3(EMB / 64, NTOK / 64, 1), 128>>>(bo, nullptr, nullptr, out, 3);
}